// round 2
// baseline (speedup 1.0000x reference)
#include <cuda_runtime.h>

// Problem constants (from reference)
#define NN 50000
#define DD 256
#define RR 16
#define EE 800000
#define KK (17 * DD)          // 4352 : 16 relation blocks + 1 self block
#define ROW4 (KK / 4)         // 1088 float4 per H row

// Scratch (device globals — allocation-free per harness rules)
__device__ float g_H[(size_t)NN * KK];   // ~870 MB: [node][rel*256+k | 4096+k(self)]
__device__ float g_B[(size_t)KK * DD];   // 4.4 MB : [W_rel flattened ; W_self]

// ---------------------------------------------------------------------------
// Kernel 1: concatenate W_rel (16,256,256) and W_self (256,256) into g_B.
// ---------------------------------------------------------------------------
__global__ void copyw_kernel(const float* __restrict__ wr, const float* __restrict__ ws) {
    int idx = blockIdx.x * blockDim.x + threadIdx.x;     // float4 index
    const int WR4 = RR * DD * DD / 4;                    // 262144
    const int WS4 = DD * DD / 4;                         // 16384
    float4* dst = reinterpret_cast<float4*>(g_B);
    if (idx < WR4) {
        dst[idx] = reinterpret_cast<const float4*>(wr)[idx];
    } else if (idx < WR4 + WS4) {
        dst[idx] = reinterpret_cast<const float4*>(ws)[idx - WR4];
    }
}

// ---------------------------------------------------------------------------
// Kernel 2: H[:, 0:4096] = 0 ; H[:, 4096:4352] = x   (one float4 per thread)
// ---------------------------------------------------------------------------
__global__ void init_kernel(const float* __restrict__ x) {
    long long idx = (long long)blockIdx.x * blockDim.x + threadIdx.x;
    if (idx >= (long long)NN * ROW4) return;
    int n = (int)(idx / ROW4);
    int c = (int)(idx % ROW4);
    float4 v;
    if (c < ROW4 - DD / 4) {
        v = make_float4(0.f, 0.f, 0.f, 0.f);
    } else {
        v = reinterpret_cast<const float4*>(x)[(long long)n * (DD / 4) + (c - (ROW4 - DD / 4))];
    }
    reinterpret_cast<float4*>(g_H)[idx] = v;
}

// ---------------------------------------------------------------------------
// Kernel 3: edge scatter. 64 threads per edge; each thread moves one float4
// of x[src] into H[dst][rel] via vector reduction atomics (sm_90+).
// NOTE: edge_index/edge_type are int32 (JAX default x64-disabled downcasts
// the reference's int64 request). Bounds guard keeps a dtype surprise from
// becoming an IMA.
// ---------------------------------------------------------------------------
__global__ void scatter_kernel(const float* __restrict__ x,
                               const int* __restrict__ ei,
                               const int* __restrict__ et) {
    int e = blockIdx.x * 4 + (threadIdx.x >> 6);
    if (e >= EE) return;
    int lane = threadIdx.x & 63;
    int src = ei[e];
    int dst = ei[EE + e];
    int rel = et[e];
    if ((unsigned)src >= NN || (unsigned)dst >= NN || (unsigned)rel >= RR) return;
    float4 v = *reinterpret_cast<const float4*>(x + (long long)src * DD + lane * 4);
    float* p = g_H + (long long)dst * KK + rel * DD + lane * 4;
    asm volatile("red.global.add.v4.f32 [%0], {%1,%2,%3,%4};"
                 :: "l"(p), "f"(v.x), "f"(v.y), "f"(v.z), "f"(v.w)
                 : "memory");
}

// ---------------------------------------------------------------------------
// Kernel 4: C = relu(H(50000x4352) @ g_B(4352x256) + bias)
// Classic SIMT SGEMM: 128x128 block tile, BK=16, 256 threads, 8x8 per thread.
// ---------------------------------------------------------------------------
#define BM 128
#define BN 128
#define BK 16

__global__ __launch_bounds__(256)
void gemm_kernel(const float* __restrict__ bias, float* __restrict__ C) {
    __shared__ float As[BK][BM];   // A stored transposed for broadcast reads
    __shared__ float Bs[BK][BN];

    const int tid = threadIdx.x;
    const int tx = tid & 15;       // micro-tile col group (N)
    const int ty = tid >> 4;       // micro-tile row group (M)
    const int rowBase = blockIdx.y * BM;
    const int colBase = blockIdx.x * BN;

    float acc[8][8];
#pragma unroll
    for (int m = 0; m < 8; ++m)
#pragma unroll
        for (int n = 0; n < 8; ++n) acc[m][n] = 0.f;

    // A-tile load map: 128 rows x 4 float4-cols = 512 float4; 2 per thread
    const int aR  = tid >> 1;            // 0..127
    const int aC4 = (tid & 1) * 2;       // {0,2} -> float4 cols aC4, aC4+1
    // B-tile load map: 16 rows x 32 float4-cols = 512 float4; 2 per thread
    const int bR  = tid >> 5;            // 0..7 (+8 on 2nd iter)
    const int bC4 = tid & 31;            // 0..31

    const float* A = g_H;
    const float* B = g_B;

    for (int k0 = 0; k0 < KK; k0 += BK) {
        // Load A tile (guard M edge), transpose into As[k][row]
#pragma unroll
        for (int i = 0; i < 2; ++i) {
            int gr = rowBase + aR;
            int c4 = aC4 + i;
            float4 v = make_float4(0.f, 0.f, 0.f, 0.f);
            if (gr < NN)
                v = *reinterpret_cast<const float4*>(A + (long long)gr * KK + k0 + c4 * 4);
            As[c4 * 4 + 0][aR] = v.x;
            As[c4 * 4 + 1][aR] = v.y;
            As[c4 * 4 + 2][aR] = v.z;
            As[c4 * 4 + 3][aR] = v.w;
        }
        // Load B tile (always in range: K=4352 % 16 == 0, N=256 exact)
#pragma unroll
        for (int i = 0; i < 2; ++i) {
            int kk = bR + i * 8;
            float4 v = *reinterpret_cast<const float4*>(
                B + (long long)(k0 + kk) * DD + colBase + bC4 * 4);
            *reinterpret_cast<float4*>(&Bs[kk][bC4 * 4]) = v;
        }
        __syncthreads();

#pragma unroll
        for (int k = 0; k < BK; ++k) {
            float ra[8], rb[8];
            *reinterpret_cast<float4*>(&ra[0]) = *reinterpret_cast<const float4*>(&As[k][ty * 8]);
            *reinterpret_cast<float4*>(&ra[4]) = *reinterpret_cast<const float4*>(&As[k][ty * 8 + 4]);
            *reinterpret_cast<float4*>(&rb[0]) = *reinterpret_cast<const float4*>(&Bs[k][tx * 8]);
            *reinterpret_cast<float4*>(&rb[4]) = *reinterpret_cast<const float4*>(&Bs[k][tx * 8 + 4]);
#pragma unroll
            for (int m = 0; m < 8; ++m)
#pragma unroll
                for (int n = 0; n < 8; ++n)
                    acc[m][n] += ra[m] * rb[n];
        }
        __syncthreads();
    }

    // Epilogue: + bias, relu, store
#pragma unroll
    for (int m = 0; m < 8; ++m) {
        int gr = rowBase + ty * 8 + m;
        if (gr >= NN) continue;
#pragma unroll
        for (int n = 0; n < 8; n += 4) {
            int gc = colBase + tx * 8 + n;
            float4 v;
            v.x = fmaxf(acc[m][n + 0] + bias[gc + 0], 0.f);
            v.y = fmaxf(acc[m][n + 1] + bias[gc + 1], 0.f);
            v.z = fmaxf(acc[m][n + 2] + bias[gc + 2], 0.f);
            v.w = fmaxf(acc[m][n + 3] + bias[gc + 3], 0.f);
            *reinterpret_cast<float4*>(C + (long long)gr * DD + gc) = v;
        }
    }
}

// ---------------------------------------------------------------------------
extern "C" void kernel_launch(void* const* d_in, const int* in_sizes, int n_in,
                              void* d_out, int out_size) {
    const float* x    = (const float*)d_in[0];
    const int*   ei   = (const int*)d_in[1];     // (2, E) int32 (JAX x64-off)
    const int*   et   = (const int*)d_in[2];     // (E,)  int32
    const float* wr   = (const float*)d_in[3];   // (16,256,256)
    const float* ws   = (const float*)d_in[4];   // (256,256)
    const float* bias = (const float*)d_in[5];   // (256,)
    float*       out  = (float*)d_out;           // (50000,256)

    (void)in_sizes; (void)n_in; (void)out_size;

    // 1) build concatenated weight matrix (4352 x 256)
    copyw_kernel<<<(RR * DD * DD / 4 + DD * DD / 4 + 255) / 256, 256>>>(wr, ws);

    // 2) H = [zeros | x]
    long long initTotal = (long long)NN * ROW4;
    init_kernel<<<(unsigned)((initTotal + 255) / 256), 256>>>(x);

    // 3) scatter edges into H (vector fp32 reduction atomics)
    scatter_kernel<<<(EE + 3) / 4, 256>>>(x, ei, et);

    // 4) one dense GEMM + bias + relu
    dim3 grid(DD / BN, (NN + BM - 1) / BM);   // (2, 391)
    gemm_kernel<<<grid, 256>>>(bias, out);
}

// round 4
// speedup vs baseline: 2.0054x; 2.0054x over previous
#include <cuda_runtime.h>
#include <cuda_bf16.h>
#include <cstdint>

// Problem constants
#define NN 50000
#define NNPAD 50048              // 391*128; pad rows stay zero (globals zero-init)
#define DD 256
#define RR 16
#define EE 800000
#define KK (17 * DD)             // 4352 output cols: 16 relation blocks + self

// Scratch (device globals; zero-initialized; allocation-free)
__device__ __nv_bfloat16 g_xh[(size_t)NNPAD * DD];    // x hi
__device__ __nv_bfloat16 g_xl[(size_t)NNPAD * DD];    // x lo
__device__ __nv_bfloat16 g_bth[(size_t)KK * DD];      // B^T hi [j][k]
__device__ __nv_bfloat16 g_btl[(size_t)KK * DD];      // B^T lo
__device__ float         g_XW[(size_t)NN * KK];       // x @ [W_rel | W_self]

// ---------------------------------------------------------------------------
__device__ __forceinline__ uint32_t smem_u32(const void* p) {
    uint32_t a;
    asm("{ .reg .u64 t; cvta.to.shared.u64 t, %1; cvt.u32.u64 %0, t; }" : "=r"(a) : "l"(p));
    return a;
}

#define LDSM4(r, addr)                                                        \
    asm volatile("ldmatrix.sync.aligned.m8n8.x4.shared.b16 {%0,%1,%2,%3}, [%4];" \
        : "=r"((r)[0]), "=r"((r)[1]), "=r"((r)[2]), "=r"((r)[3]) : "r"(addr))

#define MMA(d, a, b)                                                          \
    asm volatile("mma.sync.aligned.m16n8k16.row.col.f32.bf16.bf16.f32 "       \
        "{%0,%1,%2,%3}, {%4,%5,%6,%7}, {%8,%9}, {%0,%1,%2,%3};"               \
        : "+f"((d)[0]), "+f"((d)[1]), "+f"((d)[2]), "+f"((d)[3])              \
        : "r"((a)[0]), "r"((a)[1]), "r"((a)[2]), "r"((a)[3]),                 \
          "r"((b)[0]), "r"((b)[1]))

// ---------------------------------------------------------------------------
// Prep 1: split x (fp32) into bf16 hi + lo
// ---------------------------------------------------------------------------
__global__ void splitx_kernel(const float* __restrict__ x) {
    long long i = (long long)blockIdx.x * blockDim.x + threadIdx.x;
    if (i >= (long long)NN * DD) return;
    float f = x[i];
    __nv_bfloat16 hi = __float2bfloat16_rn(f);
    __nv_bfloat16 lo = __float2bfloat16_rn(f - __bfloat162float(hi));
    g_xh[i] = hi;
    g_xl[i] = lo;
}

// ---------------------------------------------------------------------------
// Prep 2: B^T hi/lo: Bt[j][k] = W[k][j]; j<4096 -> W_rel[j>>8][k][j&255],
//         else W_self[k][j-4096]
// ---------------------------------------------------------------------------
__global__ void buildbt_kernel(const float* __restrict__ wr, const float* __restrict__ ws) {
    int idx = blockIdx.x * blockDim.x + threadIdx.x;
    if (idx >= KK * DD) return;
    int j = idx >> 8;
    int k = idx & 255;
    float w;
    if (j < RR * DD) {
        int r = j >> 8, h = j & 255;
        w = wr[((size_t)r * DD + k) * DD + h];
    } else {
        w = ws[(size_t)k * DD + (j - RR * DD)];
    }
    __nv_bfloat16 hi = __float2bfloat16_rn(w);
    __nv_bfloat16 lo = __float2bfloat16_rn(w - __bfloat162float(hi));
    g_bth[idx] = hi;
    g_btl[idx] = lo;
}

// ---------------------------------------------------------------------------
// GEMM: g_XW(50000x4352) = x(50000x256) @ B(256x4352), fp32 via 3-term bf16
// split on mma.sync.m16n8k16. Tile 128x128, BK=32, 8 warps (2x4), warp tile
// 64x32, double-buffered SMEM with register prefetch.
// SMEM per buffer (40960B): Ah[128][40] Al[128][40] Bh[128][40] Bl[128][40]
// (rows padded 32->40 bf16 = 80B; ldmatrix banks 20r mod 32: conflict-free)
// ---------------------------------------------------------------------------
#define BK 32
#define HL_OFF 10240             // 128 rows * 80B
#define B_OFF 20480
#define BUF_OFF 40960
#define SMEM_BYTES 81920

__global__ void __launch_bounds__(256) mma_gemm_kernel() {
    extern __shared__ char sm[];
    const uint32_t sb = smem_u32(sm);
    const int tid = threadIdx.x, warp = tid >> 5, lane = tid & 31;
    const int wm = warp & 1, wn = warp >> 1;
    const size_t mBase = (size_t)blockIdx.y * 128;
    const int nBase = blockIdx.x * 128;

    float acc[4][4][4];
#pragma unroll
    for (int a = 0; a < 4; ++a)
#pragma unroll
        for (int b = 0; b < 4; ++b)
#pragma unroll
            for (int c = 0; c < 4; ++c) acc[a][b][c] = 0.f;

    uint4 av[4], bv[4];   // ldg staging

    auto ldg = [&](int c) {
        const int kOff = c * BK;
#pragma unroll
        for (int i = 0; i < 4; ++i) {
            int idx = tid + i * 256;                 // 0..1023
            int half = idx >> 9;                     // 0:hi 1:lo
            int r = (idx >> 2) & 127, v = idx & 3;
            const __nv_bfloat16* s = half ? g_xl : g_xh;
            av[i] = *(const uint4*)(s + (mBase + r) * DD + kOff + v * 8);
            const __nv_bfloat16* t = half ? g_btl : g_bth;
            bv[i] = *(const uint4*)(t + (size_t)(nBase + r) * DD + kOff + v * 8);
        }
    };
    auto sts = [&](int b) {
        char* base = sm + b * BUF_OFF;
#pragma unroll
        for (int i = 0; i < 4; ++i) {
            int idx = tid + i * 256;
            int half = idx >> 9;
            int r = (idx >> 2) & 127, v = idx & 3;
            *(uint4*)(base + half * HL_OFF + r * 80 + v * 16) = av[i];
            *(uint4*)(base + B_OFF + half * HL_OFF + r * 80 + v * 16) = bv[i];
        }
    };
    auto compute = [&](int b) {
        const uint32_t Ab = sb + b * BUF_OFF;
        const uint32_t Bb = Ab + B_OFF;
#pragma unroll
        for (int ks = 0; ks < 2; ++ks) {
            uint32_t ah[4][4], al[4][4];
            const int arow = wm * 64 + (lane & 15);
            const uint32_t acol = ((lane >> 4) * 16) + ks * 32;
#pragma unroll
            for (int mt = 0; mt < 4; ++mt) {
                uint32_t ad = Ab + (uint32_t)(arow + mt * 16) * 80 + acol;
                LDSM4(ah[mt], ad);
                LDSM4(al[mt], ad + HL_OFF);
            }
            uint32_t bh[2][4], bl[2][4];
            const int brow = (lane & 7) + ((lane >> 4) << 3);
            const uint32_t bcol = (((lane >> 3) & 1) * 16) + ks * 32;
#pragma unroll
            for (int ng = 0; ng < 2; ++ng) {
                uint32_t bd = Bb + (uint32_t)(wn * 32 + ng * 16 + brow) * 80 + bcol;
                LDSM4(bh[ng], bd);
                LDSM4(bl[ng], bd + HL_OFF);
            }
#pragma unroll
            for (int mt = 0; mt < 4; ++mt)
#pragma unroll
                for (int nt = 0; nt < 4; ++nt) {
                    int ng = nt >> 1, j = nt & 1;
                    MMA(acc[mt][nt], ah[mt], (&bh[ng][j * 2]));
                    MMA(acc[mt][nt], ah[mt], (&bl[ng][j * 2]));
                    MMA(acc[mt][nt], al[mt], (&bh[ng][j * 2]));
                }
        }
    };

    ldg(0); sts(0); __syncthreads();
#pragma unroll 1
    for (int c = 0; c < 8; ++c) {
        if (c < 7) ldg(c + 1);
        compute(c & 1);
        __syncthreads();
        if (c < 7) { sts((c + 1) & 1); __syncthreads(); }
    }

    // epilogue: direct fp32 stores to g_XW
#pragma unroll
    for (int mt = 0; mt < 4; ++mt) {
        int r0 = (int)mBase + wm * 64 + mt * 16 + (lane >> 2);
#pragma unroll
        for (int nt = 0; nt < 4; ++nt) {
            int col = nBase + wn * 32 + nt * 8 + 2 * (lane & 3);
            if (r0 < NN)
                *(float2*)(g_XW + (size_t)r0 * KK + col) =
                    make_float2(acc[mt][nt][0], acc[mt][nt][1]);
            if (r0 + 8 < NN)
                *(float2*)(g_XW + (size_t)(r0 + 8) * KK + col) =
                    make_float2(acc[mt][nt][2], acc[mt][nt][3]);
        }
    }
}

// ---------------------------------------------------------------------------
// Scatter: XW[dst, self] += XW[src, rel-block]. Self block (51MB) is
// L2-resident for the atomics. 64 threads/edge, red.v4.
// ---------------------------------------------------------------------------
__global__ void scatter_kernel(const int* __restrict__ ei, const int* __restrict__ et) {
    int e = blockIdx.x * 4 + (threadIdx.x >> 6);
    if (e >= EE) return;
    int lane = threadIdx.x & 63;
    int src = ei[e];
    int dst = ei[EE + e];
    int rel = et[e];
    if ((unsigned)src >= NN || (unsigned)dst >= NN || (unsigned)rel >= RR) return;
    float4 v = *(const float4*)(g_XW + (size_t)src * KK + rel * DD + lane * 4);
    float* p = g_XW + (size_t)dst * KK + RR * DD + lane * 4;
    asm volatile("red.global.add.v4.f32 [%0], {%1,%2,%3,%4};"
                 :: "l"(p), "f"(v.x), "f"(v.y), "f"(v.z), "f"(v.w) : "memory");
}

// ---------------------------------------------------------------------------
// Final: out = relu(XW[:, self] + bias)
// ---------------------------------------------------------------------------
__global__ void relu_kernel(const float* __restrict__ bias, float* __restrict__ out) {
    long long idx = (long long)blockIdx.x * blockDim.x + threadIdx.x;   // float4 idx
    if (idx >= (long long)NN * (DD / 4)) return;
    int n = (int)(idx >> 6);
    int c = (int)(idx & 63);
    float4 v = *(const float4*)(g_XW + (size_t)n * KK + RR * DD + c * 4);
    float4 b = *(const float4*)(bias + c * 4);
    float4 o;
    o.x = fmaxf(v.x + b.x, 0.f);
    o.y = fmaxf(v.y + b.y, 0.f);
    o.z = fmaxf(v.z + b.z, 0.f);
    o.w = fmaxf(v.w + b.w, 0.f);
    *(float4*)(out + (size_t)n * DD + c * 4) = o;
}

// ---------------------------------------------------------------------------
extern "C" void kernel_launch(void* const* d_in, const int* in_sizes, int n_in,
                              void* d_out, int out_size) {
    const float* x    = (const float*)d_in[0];
    const int*   ei   = (const int*)d_in[1];     // (2, E) int32
    const int*   et   = (const int*)d_in[2];     // (E,)  int32
    const float* wr   = (const float*)d_in[3];   // (16,256,256)
    const float* ws   = (const float*)d_in[4];   // (256,256)
    const float* bias = (const float*)d_in[5];   // (256,)
    float*       out  = (float*)d_out;           // (50000,256)
    (void)in_sizes; (void)n_in; (void)out_size;

    cudaFuncSetAttribute(mma_gemm_kernel, cudaFuncAttributeMaxDynamicSharedMemorySize, SMEM_BYTES);

    splitx_kernel<<<(NN * DD + 255) / 256, 256>>>(x);
    buildbt_kernel<<<(KK * DD + 255) / 256, 256>>>(wr, ws);

    dim3 grid(KK / 128, NNPAD / 128);   // (34, 391)
    mma_gemm_kernel<<<grid, 256, SMEM_BYTES>>>();

    scatter_kernel<<<(EE + 3) / 4, 256>>>(ei, et);
    relu_kernel<<<(unsigned)(((long long)NN * (DD / 4) + 255) / 256), 256>>>(bias, out);
}

// round 5
// speedup vs baseline: 3.0042x; 1.4980x over previous
#include <cuda_runtime.h>
#include <cuda_fp16.h>
#include <cstdint>

// Problem constants
#define NN 50000
#define NNPAD 50048              // 391*128; pad rows stay zero (globals zero-init)
#define DD 256
#define RR 16
#define EE 800000
#define KK (17 * DD)             // 4352 output cols: 16 relation blocks + self

// Scratch (device globals; zero-initialized; allocation-free)
__device__ __half g_xh[(size_t)NNPAD * DD];    // x hi (fp16)
__device__ __half g_xl[(size_t)NNPAD * DD];    // x lo (fp16 residual)
__device__ __half g_bt[(size_t)KK * DD];       // B^T fp16  [j][k]
__device__ float  g_XW[(size_t)NN * KK];       // x @ [W_rel | W_self]

// ---------------------------------------------------------------------------
__device__ __forceinline__ uint32_t smem_u32(const void* p) {
    uint32_t a;
    asm("{ .reg .u64 t; cvta.to.shared.u64 t, %1; cvt.u32.u64 %0, t; }" : "=r"(a) : "l"(p));
    return a;
}

#define LDSM4(r, addr)                                                        \
    asm volatile("ldmatrix.sync.aligned.m8n8.x4.shared.b16 {%0,%1,%2,%3}, [%4];" \
        : "=r"((r)[0]), "=r"((r)[1]), "=r"((r)[2]), "=r"((r)[3]) : "r"(addr))

#define MMA(d, a, b)                                                          \
    asm volatile("mma.sync.aligned.m16n8k16.row.col.f32.f16.f16.f32 "         \
        "{%0,%1,%2,%3}, {%4,%5,%6,%7}, {%8,%9}, {%0,%1,%2,%3};"               \
        : "+f"((d)[0]), "+f"((d)[1]), "+f"((d)[2]), "+f"((d)[3])              \
        : "r"((a)[0]), "r"((a)[1]), "r"((a)[2]), "r"((a)[3]),                 \
          "r"((b)[0]), "r"((b)[1]))

#define CP16(dst, src) asm volatile("cp.async.cg.shared.global [%0], [%1], 16;" :: "r"(dst), "l"(src))
#define CP_COMMIT()    asm volatile("cp.async.commit_group;" ::: "memory")
#define CP_WAIT(n)     asm volatile("cp.async.wait_group %0;" :: "n"(n) : "memory")

// ---------------------------------------------------------------------------
// Prep 1: split x (fp32) into fp16 hi + lo (residual)
// ---------------------------------------------------------------------------
__global__ void splitx_kernel(const float* __restrict__ x) {
    long long i = (long long)blockIdx.x * blockDim.x + threadIdx.x;
    if (i >= (long long)NN * DD) return;
    float f = x[i];
    __half hi = __float2half_rn(f);
    __half lo = __float2half_rn(f - __half2float(hi));
    g_xh[i] = hi;
    g_xl[i] = lo;
}

// ---------------------------------------------------------------------------
// Prep 2: B^T fp16: Bt[j][k] = W[k][j]; j<4096 -> W_rel[j>>8][k][j&255],
//         else W_self[k][j-4096]
// ---------------------------------------------------------------------------
__global__ void buildbt_kernel(const float* __restrict__ wr, const float* __restrict__ ws) {
    int idx = blockIdx.x * blockDim.x + threadIdx.x;
    if (idx >= KK * DD) return;
    int j = idx >> 8;
    int k = idx & 255;
    float w;
    if (j < RR * DD) {
        int r = j >> 8, h = j & 255;
        w = wr[((size_t)r * DD + k) * DD + h];
    } else {
        w = ws[(size_t)k * DD + (j - RR * DD)];
    }
    g_bt[idx] = __float2half_rn(w);
}

// ---------------------------------------------------------------------------
// GEMM: g_XW(50000x4352) = x @ B, fp32 via 2-term fp16 split
// (x_hi + x_lo) @ w_hi on mma.sync.m16n8k16. Tile 128x128, BK=32, 8 warps
// (2x4), warp tile 64x32, cp.async double buffer.
// SMEM per buffer (30720B): Ah[128][40] Al[128][40] Bh[128][40]
// (rows padded 32->40 half = 80B)
// ---------------------------------------------------------------------------
#define PL_OFF 10240             // plane: 128 rows * 80B
#define BUF_OFF 30720
#define SMEM_BYTES 61440

__global__ void __launch_bounds__(256, 2) mma_gemm_kernel() {
    extern __shared__ char sm[];
    const uint32_t sb = smem_u32(sm);
    const int tid = threadIdx.x, warp = tid >> 5, lane = tid & 31;
    const int wm = warp & 1, wn = warp >> 1;
    const size_t mBase = (size_t)blockIdx.y * 128;
    const int nBase = blockIdx.x * 128;

    float acc[4][4][4];
#pragma unroll
    for (int a = 0; a < 4; ++a)
#pragma unroll
        for (int b = 0; b < 4; ++b)
#pragma unroll
            for (int c = 0; c < 4; ++c) acc[a][b][c] = 0.f;

    // chunk loader: 1536 x 16B cp.async (Ah 512, Al 512, Bh 512) -> 6/thread
    auto load = [&](int c, int b) {
        const int kOff = c * 32;
        const uint32_t dbase = sb + b * BUF_OFF;
#pragma unroll
        for (int i = 0; i < 6; ++i) {
            int idx = tid + i * 256;                 // 0..1535
            int part = idx >> 9;                     // 0:Ah 1:Al 2:Bh
            int r = (idx >> 2) & 127, v = idx & 3;
            const __half* src;
            if (part == 0)      src = g_xh + (mBase + r) * DD + kOff + v * 8;
            else if (part == 1) src = g_xl + (mBase + r) * DD + kOff + v * 8;
            else                src = g_bt + (size_t)(nBase + r) * DD + kOff + v * 8;
            CP16(dbase + part * PL_OFF + r * 80 + v * 16, src);
        }
    };

    auto compute = [&](int b) {
        const uint32_t Ab = sb + b * BUF_OFF;
        const uint32_t Bb = Ab + 2 * PL_OFF;
#pragma unroll
        for (int ks = 0; ks < 2; ++ks) {
            uint32_t ah[4][4], al[4][4];
            const int arow = wm * 64 + (lane & 15);
            const uint32_t acol = ((lane >> 4) * 16) + ks * 32;
#pragma unroll
            for (int mt = 0; mt < 4; ++mt) {
                uint32_t ad = Ab + (uint32_t)(arow + mt * 16) * 80 + acol;
                LDSM4(ah[mt], ad);
                LDSM4(al[mt], ad + PL_OFF);
            }
            uint32_t bh[2][4];
            const int brow = (lane & 7) + ((lane >> 4) << 3);
            const uint32_t bcol = (((lane >> 3) & 1) * 16) + ks * 32;
#pragma unroll
            for (int ng = 0; ng < 2; ++ng) {
                uint32_t bd = Bb + (uint32_t)(wn * 32 + ng * 16 + brow) * 80 + bcol;
                LDSM4(bh[ng], bd);
            }
#pragma unroll
            for (int mt = 0; mt < 4; ++mt)
#pragma unroll
                for (int nt = 0; nt < 4; ++nt) {
                    int ng = nt >> 1, j = nt & 1;
                    MMA(acc[mt][nt], ah[mt], (&bh[ng][j * 2]));
                    MMA(acc[mt][nt], al[mt], (&bh[ng][j * 2]));
                }
        }
    };

    load(0, 0);
    CP_COMMIT();
#pragma unroll 1
    for (int c = 0; c < 8; ++c) {
        if (c < 7) {
            load(c + 1, (c + 1) & 1);
            CP_COMMIT();
            CP_WAIT(1);
        } else {
            CP_WAIT(0);
        }
        __syncthreads();
        compute(c & 1);
        __syncthreads();
    }

    // epilogue: direct fp32 stores to g_XW
#pragma unroll
    for (int mt = 0; mt < 4; ++mt) {
        int r0 = (int)mBase + wm * 64 + mt * 16 + (lane >> 2);
#pragma unroll
        for (int nt = 0; nt < 4; ++nt) {
            int col = nBase + wn * 32 + nt * 8 + 2 * (lane & 3);
            if (r0 < NN)
                *(float2*)(g_XW + (size_t)r0 * KK + col) =
                    make_float2(acc[mt][nt][0], acc[mt][nt][1]);
            if (r0 + 8 < NN)
                *(float2*)(g_XW + (size_t)(r0 + 8) * KK + col) =
                    make_float2(acc[mt][nt][2], acc[mt][nt][3]);
        }
    }
}

// ---------------------------------------------------------------------------
// Scatter: XW[dst, self] += XW[src, rel-block]. Self block (51MB) is
// L2-resident for the atomics. 64 threads/edge, red.v4.
// ---------------------------------------------------------------------------
__global__ void scatter_kernel(const int* __restrict__ ei, const int* __restrict__ et) {
    int e = blockIdx.x * 4 + (threadIdx.x >> 6);
    if (e >= EE) return;
    int lane = threadIdx.x & 63;
    int src = ei[e];
    int dst = ei[EE + e];
    int rel = et[e];
    if ((unsigned)src >= NN || (unsigned)dst >= NN || (unsigned)rel >= RR) return;
    float4 v = *(const float4*)(g_XW + (size_t)src * KK + rel * DD + lane * 4);
    float* p = g_XW + (size_t)dst * KK + RR * DD + lane * 4;
    asm volatile("red.global.add.v4.f32 [%0], {%1,%2,%3,%4};"
                 :: "l"(p), "f"(v.x), "f"(v.y), "f"(v.z), "f"(v.w) : "memory");
}

// ---------------------------------------------------------------------------
// Final: out = relu(XW[:, self] + bias)
// ---------------------------------------------------------------------------
__global__ void relu_kernel(const float* __restrict__ bias, float* __restrict__ out) {
    long long idx = (long long)blockIdx.x * blockDim.x + threadIdx.x;   // float4 idx
    if (idx >= (long long)NN * (DD / 4)) return;
    int n = (int)(idx >> 6);
    int c = (int)(idx & 63);
    float4 v = *(const float4*)(g_XW + (size_t)n * KK + RR * DD + c * 4);
    float4 b = *(const float4*)(bias + c * 4);
    float4 o;
    o.x = fmaxf(v.x + b.x, 0.f);
    o.y = fmaxf(v.y + b.y, 0.f);
    o.z = fmaxf(v.z + b.z, 0.f);
    o.w = fmaxf(v.w + b.w, 0.f);
    *(float4*)(out + (size_t)n * DD + c * 4) = o;
}

// ---------------------------------------------------------------------------
extern "C" void kernel_launch(void* const* d_in, const int* in_sizes, int n_in,
                              void* d_out, int out_size) {
    const float* x    = (const float*)d_in[0];
    const int*   ei   = (const int*)d_in[1];     // (2, E) int32
    const int*   et   = (const int*)d_in[2];     // (E,)  int32
    const float* wr   = (const float*)d_in[3];   // (16,256,256)
    const float* ws   = (const float*)d_in[4];   // (256,256)
    const float* bias = (const float*)d_in[5];   // (256,)
    float*       out  = (float*)d_out;           // (50000,256)
    (void)in_sizes; (void)n_in; (void)out_size;

    cudaFuncSetAttribute(mma_gemm_kernel, cudaFuncAttributeMaxDynamicSharedMemorySize, SMEM_BYTES);

    splitx_kernel<<<(NN * DD + 255) / 256, 256>>>(x);
    buildbt_kernel<<<(KK * DD + 255) / 256, 256>>>(wr, ws);

    dim3 grid(KK / 128, NNPAD / 128);   // (34, 391)
    mma_gemm_kernel<<<grid, 256, SMEM_BYTES>>>();

    scatter_kernel<<<(EE + 3) / 4, 256>>>(ei, et);
    relu_kernel<<<(unsigned)(((long long)NN * (DD / 4) + 255) / 256), 256>>>(bias, out);
}

// round 7
// speedup vs baseline: 3.9981x; 1.3309x over previous
#include <cuda_runtime.h>
#include <cuda_fp16.h>
#include <cstdint>

// Problem constants
#define NN 50000
#define NNPAD 50048              // 391*128; pad rows stay zero (globals zero-init)
#define DD 256
#define RR 16
#define EE 800000
#define KK (17 * DD)             // 4352 output cols: 16 relation blocks + self

// Scratch (device globals; zero-initialized; allocation-free)
__device__ __half g_xh[(size_t)NNPAD * DD];    // x (fp16)
__device__ __half g_bt[(size_t)KK * DD];       // B^T fp16  [j][k]
__device__ float  g_XW[(size_t)NN * KK];       // x @ [W_rel | W_self]

// ---------------------------------------------------------------------------
__device__ __forceinline__ uint32_t smem_u32(const void* p) {
    uint32_t a;
    asm("{ .reg .u64 t; cvta.to.shared.u64 t, %1; cvt.u32.u64 %0, t; }" : "=r"(a) : "l"(p));
    return a;
}

#define LDSM4(r, addr)                                                        \
    asm volatile("ldmatrix.sync.aligned.m8n8.x4.shared.b16 {%0,%1,%2,%3}, [%4];" \
        : "=r"((r)[0]), "=r"((r)[1]), "=r"((r)[2]), "=r"((r)[3]) : "r"(addr))

#define MMA(d, a, b)                                                          \
    asm volatile("mma.sync.aligned.m16n8k16.row.col.f32.f16.f16.f32 "         \
        "{%0,%1,%2,%3}, {%4,%5,%6,%7}, {%8,%9}, {%0,%1,%2,%3};"               \
        : "+f"((d)[0]), "+f"((d)[1]), "+f"((d)[2]), "+f"((d)[3])              \
        : "r"((a)[0]), "r"((a)[1]), "r"((a)[2]), "r"((a)[3]),                 \
          "r"((b)[0]), "r"((b)[1]))

#define CP16(dst, src) asm volatile("cp.async.cg.shared.global [%0], [%1], 16;" :: "r"(dst), "l"(src))
#define CP_COMMIT()    asm volatile("cp.async.commit_group;" ::: "memory")
#define CP_WAIT(n)     asm volatile("cp.async.wait_group %0;" :: "n"(n) : "memory")

// ---------------------------------------------------------------------------
// Prep 1: x fp32 -> fp16
// ---------------------------------------------------------------------------
__global__ void cvtx_kernel(const float* __restrict__ x) {
    long long i = (long long)blockIdx.x * blockDim.x + threadIdx.x;
    if (i >= (long long)NN * DD) return;
    g_xh[i] = __float2half_rn(x[i]);
}

// ---------------------------------------------------------------------------
// Prep 2: B^T fp16: Bt[j][k] = W[k][j]; j<4096 -> W_rel[j>>8][k][j&255],
//         else W_self[k][j-4096]
// ---------------------------------------------------------------------------
__global__ void buildbt_kernel(const float* __restrict__ wr, const float* __restrict__ ws) {
    int idx = blockIdx.x * blockDim.x + threadIdx.x;
    if (idx >= KK * DD) return;
    int j = idx >> 8;
    int k = idx & 255;
    float w;
    if (j < RR * DD) {
        int r = j >> 8, h = j & 255;
        w = wr[((size_t)r * DD + k) * DD + h];
    } else {
        w = ws[(size_t)k * DD + (j - RR * DD)];
    }
    g_bt[idx] = __float2half_rn(w);
}

// ---------------------------------------------------------------------------
// GEMM: g_XW(50000x4352) = x @ B, plain fp16 mma.sync.m16n8k16 with fp32
// accum. Tile 128x128, BK=32, 8 warps (2x4), warp tile 64x32, cp.async
// double buffer. SMEM per buffer (20480B): A[128][40] B[128][40]
// (rows padded 32->40 half = 80B; ldmatrix conflict-free)
// ---------------------------------------------------------------------------
#define PL_OFF 10240             // plane: 128 rows * 80B
#define BUF_OFF 20480
#define SMEM_BYTES 40960

__global__ void __launch_bounds__(256, 2) mma_gemm_kernel() {
    extern __shared__ char sm[];
    const uint32_t sb = smem_u32(sm);
    const int tid = threadIdx.x, warp = tid >> 5, lane = tid & 31;
    const int wm = warp & 1, wn = warp >> 1;
    const size_t mBase = (size_t)blockIdx.y * 128;
    const int nBase = blockIdx.x * 128;

    float acc[4][4][4];
#pragma unroll
    for (int a = 0; a < 4; ++a)
#pragma unroll
        for (int b = 0; b < 4; ++b)
#pragma unroll
            for (int c = 0; c < 4; ++c) acc[a][b][c] = 0.f;

    // chunk loader: 1024 x 16B cp.async (A 512, B 512) -> 4/thread
    auto load = [&](int c, int b) {
        const int kOff = c * 32;
        const uint32_t dbase = sb + b * BUF_OFF;
#pragma unroll
        for (int i = 0; i < 4; ++i) {
            int idx = tid + i * 256;                 // 0..1023
            int part = idx >> 9;                     // 0:A 1:B
            int r = (idx >> 2) & 127, v = idx & 3;
            const __half* src = part
                ? g_bt + (size_t)(nBase + r) * DD + kOff + v * 8
                : g_xh + (mBase + r) * DD + kOff + v * 8;
            CP16(dbase + part * PL_OFF + r * 80 + v * 16, src);
        }
    };

    auto compute = [&](int b) {
        const uint32_t Ab = sb + b * BUF_OFF;
        const uint32_t Bb = Ab + PL_OFF;
#pragma unroll
        for (int ks = 0; ks < 2; ++ks) {
            uint32_t ah[4][4];
            const int arow = wm * 64 + (lane & 15);
            const uint32_t acol = ((lane >> 4) * 16) + ks * 32;
#pragma unroll
            for (int mt = 0; mt < 4; ++mt) {
                uint32_t ad = Ab + (uint32_t)(arow + mt * 16) * 80 + acol;
                LDSM4(ah[mt], ad);
            }
            uint32_t bh[2][4];
            const int brow = (lane & 7) + ((lane >> 4) << 3);
            const uint32_t bcol = (((lane >> 3) & 1) * 16) + ks * 32;
#pragma unroll
            for (int ng = 0; ng < 2; ++ng) {
                uint32_t bd = Bb + (uint32_t)(wn * 32 + ng * 16 + brow) * 80 + bcol;
                LDSM4(bh[ng], bd);
            }
#pragma unroll
            for (int mt = 0; mt < 4; ++mt)
#pragma unroll
                for (int nt = 0; nt < 4; ++nt) {
                    int ng = nt >> 1, j = nt & 1;
                    MMA(acc[mt][nt], ah[mt], (&bh[ng][j * 2]));
                }
        }
    };

    load(0, 0);
    CP_COMMIT();
#pragma unroll 1
    for (int c = 0; c < 8; ++c) {
        if (c < 7) {
            load(c + 1, (c + 1) & 1);
            CP_COMMIT();
            CP_WAIT(1);
        } else {
            CP_WAIT(0);
        }
        __syncthreads();
        compute(c & 1);
        __syncthreads();
    }

    // epilogue: direct fp32 stores to g_XW
#pragma unroll
    for (int mt = 0; mt < 4; ++mt) {
        int r0 = (int)mBase + wm * 64 + mt * 16 + (lane >> 2);
#pragma unroll
        for (int nt = 0; nt < 4; ++nt) {
            int col = nBase + wn * 32 + nt * 8 + 2 * (lane & 3);
            if (r0 < NN)
                *(float2*)(g_XW + (size_t)r0 * KK + col) =
                    make_float2(acc[mt][nt][0], acc[mt][nt][1]);
            if (r0 + 8 < NN)
                *(float2*)(g_XW + (size_t)(r0 + 8) * KK + col) =
                    make_float2(acc[mt][nt][2], acc[mt][nt][3]);
        }
    }
}

// ---------------------------------------------------------------------------
// Scatter: XW[dst, self] += XW[src, rel-block]. Self block (51MB) is
// L2-resident for the atomics. 64 threads/edge, red.v4.
// ---------------------------------------------------------------------------
__global__ void scatter_kernel(const int* __restrict__ ei, const int* __restrict__ et) {
    int e = blockIdx.x * 4 + (threadIdx.x >> 6);
    if (e >= EE) return;
    int lane = threadIdx.x & 63;
    int src = ei[e];
    int dst = ei[EE + e];
    int rel = et[e];
    if ((unsigned)src >= NN || (unsigned)dst >= NN || (unsigned)rel >= RR) return;
    float4 v = *(const float4*)(g_XW + (size_t)src * KK + rel * DD + lane * 4);
    float* p = g_XW + (size_t)dst * KK + RR * DD + lane * 4;
    asm volatile("red.global.add.v4.f32 [%0], {%1,%2,%3,%4};"
                 :: "l"(p), "f"(v.x), "f"(v.y), "f"(v.z), "f"(v.w) : "memory");
}

// ---------------------------------------------------------------------------
// Final: out = relu(XW[:, self] + bias)
// ---------------------------------------------------------------------------
__global__ void relu_kernel(const float* __restrict__ bias, float* __restrict__ out) {
    long long idx = (long long)blockIdx.x * blockDim.x + threadIdx.x;   // float4 idx
    if (idx >= (long long)NN * (DD / 4)) return;
    int n = (int)(idx >> 6);
    int c = (int)(idx & 63);
    float4 v = *(const float4*)(g_XW + (size_t)n * KK + RR * DD + c * 4);
    float4 b = *(const float4*)(bias + c * 4);
    float4 o;
    o.x = fmaxf(v.x + b.x, 0.f);
    o.y = fmaxf(v.y + b.y, 0.f);
    o.z = fmaxf(v.z + b.z, 0.f);
    o.w = fmaxf(v.w + b.w, 0.f);
    *(float4*)(out + (size_t)n * DD + c * 4) = o;
}

// ---------------------------------------------------------------------------
extern "C" void kernel_launch(void* const* d_in, const int* in_sizes, int n_in,
                              void* d_out, int out_size) {
    const float* x    = (const float*)d_in[0];
    const int*   ei   = (const int*)d_in[1];     // (2, E) int32
    const int*   et   = (const int*)d_in[2];     // (E,)  int32
    const float* wr   = (const float*)d_in[3];   // (16,256,256)
    const float* ws   = (const float*)d_in[4];   // (256,256)
    const float* bias = (const float*)d_in[5];   // (256,)
    float*       out  = (float*)d_out;           // (50000,256)
    (void)in_sizes; (void)n_in; (void)out_size;

    cudaFuncSetAttribute(mma_gemm_kernel, cudaFuncAttributeMaxDynamicSharedMemorySize, SMEM_BYTES);

    cvtx_kernel<<<(NN * DD + 255) / 256, 256>>>(x);
    buildbt_kernel<<<(KK * DD + 255) / 256, 256>>>(wr, ws);

    dim3 grid(KK / 128, NNPAD / 128);   // (34, 391)
    mma_gemm_kernel<<<grid, 256, SMEM_BYTES>>>();

    scatter_kernel<<<(EE + 3) / 4, 256>>>(ei, et);
    relu_kernel<<<(unsigned)(((long long)NN * (DD / 4) + 255) / 256), 256>>>(bias, out);
}

// round 8
// speedup vs baseline: 4.3107x; 1.0782x over previous
#include <cuda_runtime.h>
#include <cuda_fp16.h>
#include <cstdint>

// Problem constants
#define NN 50000
#define NNPAD 50048              // 391*128; pad rows stay zero (globals zero-init)
#define DD 256
#define RR 16
#define EE 800000
#define KK (17 * DD)             // 4352 GEMM cols: 16 relation blocks + self
#define RELC (RR * DD)           // 4096 relation cols

// Scratch (device globals; zero-initialized; allocation-free)
__device__ __half g_xh[(size_t)NNPAD * DD];      // x (fp16)
__device__ __half g_bt[(size_t)KK * DD];         // B^T fp16 [j][k]
__device__ __half g_XWrel[(size_t)NN * RELC];    // 410MB fp16 messages
__device__ float  g_self[(size_t)NN * DD];       // 51MB  self term + scatter accum

// ---------------------------------------------------------------------------
__device__ __forceinline__ uint32_t smem_u32(const void* p) {
    uint32_t a;
    asm("{ .reg .u64 t; cvta.to.shared.u64 t, %1; cvt.u32.u64 %0, t; }" : "=r"(a) : "l"(p));
    return a;
}

#define LDSM4(r, addr)                                                        \
    asm volatile("ldmatrix.sync.aligned.m8n8.x4.shared.b16 {%0,%1,%2,%3}, [%4];" \
        : "=r"((r)[0]), "=r"((r)[1]), "=r"((r)[2]), "=r"((r)[3]) : "r"(addr))

#define MMA(d, a, b)                                                          \
    asm volatile("mma.sync.aligned.m16n8k16.row.col.f32.f16.f16.f32 "         \
        "{%0,%1,%2,%3}, {%4,%5,%6,%7}, {%8,%9}, {%0,%1,%2,%3};"               \
        : "+f"((d)[0]), "+f"((d)[1]), "+f"((d)[2]), "+f"((d)[3])              \
        : "r"((a)[0]), "r"((a)[1]), "r"((a)[2]), "r"((a)[3]),                 \
          "r"((b)[0]), "r"((b)[1]))

#define CP16(dst, src) asm volatile("cp.async.cg.shared.global [%0], [%1], 16;" :: "r"(dst), "l"(src))
#define CP_COMMIT()    asm volatile("cp.async.commit_group;" ::: "memory")
#define CP_WAIT(n)     asm volatile("cp.async.wait_group %0;" :: "n"(n) : "memory")

// ---------------------------------------------------------------------------
// Prep 1: x fp32 -> fp16
// ---------------------------------------------------------------------------
__global__ void cvtx_kernel(const float* __restrict__ x) {
    long long i = (long long)blockIdx.x * blockDim.x + threadIdx.x;
    if (i >= (long long)NN * DD) return;
    g_xh[i] = __float2half_rn(x[i]);
}

// ---------------------------------------------------------------------------
// Prep 2: B^T fp16: Bt[j][k] = W[k][j]; j<4096 -> W_rel[j>>8][k][j&255],
//         else W_self[k][j-4096]
// ---------------------------------------------------------------------------
__global__ void buildbt_kernel(const float* __restrict__ wr, const float* __restrict__ ws) {
    int idx = blockIdx.x * blockDim.x + threadIdx.x;
    if (idx >= KK * DD) return;
    int j = idx >> 8;
    int k = idx & 255;
    float w;
    if (j < RELC) {
        int r = j >> 8, h = j & 255;
        w = wr[((size_t)r * DD + k) * DD + h];
    } else {
        w = ws[(size_t)k * DD + (j - RELC)];
    }
    g_bt[idx] = __float2half_rn(w);
}

// ---------------------------------------------------------------------------
// GEMM: x(50000x256) @ B(256x4352) via fp16 mma.sync, fp32 accum.
// Relation-block tiles (nBase<4096) -> g_XWrel as fp16; self tiles -> g_self
// as fp32. Tile 128x128, BK=32, 8 warps (2x4), cp.async double buffer.
// ---------------------------------------------------------------------------
#define PL_OFF 10240             // plane: 128 rows * 80B
#define BUF_OFF 20480
#define SMEM_BYTES 40960

__global__ void __launch_bounds__(256, 2) mma_gemm_kernel() {
    extern __shared__ char sm[];
    const uint32_t sb = smem_u32(sm);
    const int tid = threadIdx.x, warp = tid >> 5, lane = tid & 31;
    const int wm = warp & 1, wn = warp >> 1;
    const size_t mBase = (size_t)blockIdx.y * 128;
    const int nBase = blockIdx.x * 128;

    float acc[4][4][4];
#pragma unroll
    for (int a = 0; a < 4; ++a)
#pragma unroll
        for (int b = 0; b < 4; ++b)
#pragma unroll
            for (int c = 0; c < 4; ++c) acc[a][b][c] = 0.f;

    auto load = [&](int c, int b) {
        const int kOff = c * 32;
        const uint32_t dbase = sb + b * BUF_OFF;
#pragma unroll
        for (int i = 0; i < 4; ++i) {
            int idx = tid + i * 256;                 // 0..1023
            int part = idx >> 9;                     // 0:A 1:B
            int r = (idx >> 2) & 127, v = idx & 3;
            const __half* src = part
                ? g_bt + (size_t)(nBase + r) * DD + kOff + v * 8
                : g_xh + (mBase + r) * DD + kOff + v * 8;
            CP16(dbase + part * PL_OFF + r * 80 + v * 16, src);
        }
    };

    auto compute = [&](int b) {
        const uint32_t Ab = sb + b * BUF_OFF;
        const uint32_t Bb = Ab + PL_OFF;
#pragma unroll
        for (int ks = 0; ks < 2; ++ks) {
            uint32_t ah[4][4];
            const int arow = wm * 64 + (lane & 15);
            const uint32_t acol = ((lane >> 4) * 16) + ks * 32;
#pragma unroll
            for (int mt = 0; mt < 4; ++mt) {
                uint32_t ad = Ab + (uint32_t)(arow + mt * 16) * 80 + acol;
                LDSM4(ah[mt], ad);
            }
            uint32_t bh[2][4];
            const int brow = (lane & 7) + ((lane >> 4) << 3);
            const uint32_t bcol = (((lane >> 3) & 1) * 16) + ks * 32;
#pragma unroll
            for (int ng = 0; ng < 2; ++ng) {
                uint32_t bd = Bb + (uint32_t)(wn * 32 + ng * 16 + brow) * 80 + bcol;
                LDSM4(bh[ng], bd);
            }
#pragma unroll
            for (int mt = 0; mt < 4; ++mt)
#pragma unroll
                for (int nt = 0; nt < 4; ++nt) {
                    int ng = nt >> 1, j = nt & 1;
                    MMA(acc[mt][nt], ah[mt], (&bh[ng][j * 2]));
                }
        }
    };

    load(0, 0);
    CP_COMMIT();
#pragma unroll 1
    for (int c = 0; c < 8; ++c) {
        if (c < 7) {
            load(c + 1, (c + 1) & 1);
            CP_COMMIT();
            CP_WAIT(1);
        } else {
            CP_WAIT(0);
        }
        __syncthreads();
        compute(c & 1);
        __syncthreads();
    }

    // epilogue
    const bool isRel = nBase < RELC;
#pragma unroll
    for (int mt = 0; mt < 4; ++mt) {
        int r0 = (int)mBase + wm * 64 + mt * 16 + (lane >> 2);
#pragma unroll
        for (int nt = 0; nt < 4; ++nt) {
            int col = nBase + wn * 32 + nt * 8 + 2 * (lane & 3);
            if (isRel) {
                __half2 v01 = __floats2half2_rn(acc[mt][nt][0], acc[mt][nt][1]);
                __half2 v23 = __floats2half2_rn(acc[mt][nt][2], acc[mt][nt][3]);
                if (r0 < NN)
                    *(__half2*)(g_XWrel + (size_t)r0 * RELC + col) = v01;
                if (r0 + 8 < NN)
                    *(__half2*)(g_XWrel + (size_t)(r0 + 8) * RELC + col) = v23;
            } else {
                int sc = col - RELC;
                if (r0 < NN)
                    *(float2*)(g_self + (size_t)r0 * DD + sc) =
                        make_float2(acc[mt][nt][0], acc[mt][nt][1]);
                if (r0 + 8 < NN)
                    *(float2*)(g_self + (size_t)(r0 + 8) * DD + sc) =
                        make_float2(acc[mt][nt][2], acc[mt][nt][3]);
            }
        }
    }
}

// ---------------------------------------------------------------------------
// Scatter: g_self[dst] += fp16 message g_XWrel[src, rel]. 32 threads/edge,
// each lane: 8 halves (uint4) -> 8 floats -> two red.v4.
// ---------------------------------------------------------------------------
__global__ void scatter_kernel(const int* __restrict__ ei, const int* __restrict__ et) {
    int e = blockIdx.x * 8 + (threadIdx.x >> 5);
    if (e >= EE) return;
    int lane = threadIdx.x & 31;
    int src = ei[e];
    int dst = ei[EE + e];
    int rel = et[e];
    if ((unsigned)src >= NN || (unsigned)dst >= NN || (unsigned)rel >= RR) return;
    uint4 u = *(const uint4*)(g_XWrel + (size_t)src * RELC + rel * DD + lane * 8);
    float2 f0 = __half22float2(*(__half2*)&u.x);
    float2 f1 = __half22float2(*(__half2*)&u.y);
    float2 f2 = __half22float2(*(__half2*)&u.z);
    float2 f3 = __half22float2(*(__half2*)&u.w);
    float* p = g_self + (size_t)dst * DD + lane * 8;
    asm volatile("red.global.add.v4.f32 [%0], {%1,%2,%3,%4};"
                 :: "l"(p), "f"(f0.x), "f"(f0.y), "f"(f1.x), "f"(f1.y) : "memory");
    asm volatile("red.global.add.v4.f32 [%0], {%1,%2,%3,%4};"
                 :: "l"(p + 4), "f"(f2.x), "f"(f2.y), "f"(f3.x), "f"(f3.y) : "memory");
}

// ---------------------------------------------------------------------------
// Final: out = relu(g_self + bias)
// ---------------------------------------------------------------------------
__global__ void relu_kernel(const float* __restrict__ bias, float* __restrict__ out) {
    long long idx = (long long)blockIdx.x * blockDim.x + threadIdx.x;   // float4 idx
    if (idx >= (long long)NN * (DD / 4)) return;
    int c = (int)(idx & 63);
    float4 v = *(const float4*)(g_self + idx * 4);
    float4 b = *(const float4*)(bias + c * 4);
    float4 o;
    o.x = fmaxf(v.x + b.x, 0.f);
    o.y = fmaxf(v.y + b.y, 0.f);
    o.z = fmaxf(v.z + b.z, 0.f);
    o.w = fmaxf(v.w + b.w, 0.f);
    *(float4*)(out + idx * 4) = o;
}

// ---------------------------------------------------------------------------
extern "C" void kernel_launch(void* const* d_in, const int* in_sizes, int n_in,
                              void* d_out, int out_size) {
    const float* x    = (const float*)d_in[0];
    const int*   ei   = (const int*)d_in[1];     // (2, E) int32
    const int*   et   = (const int*)d_in[2];     // (E,)  int32
    const float* wr   = (const float*)d_in[3];   // (16,256,256)
    const float* ws   = (const float*)d_in[4];   // (256,256)
    const float* bias = (const float*)d_in[5];   // (256,)
    float*       out  = (float*)d_out;           // (50000,256)
    (void)in_sizes; (void)n_in; (void)out_size;

    cudaFuncSetAttribute(mma_gemm_kernel, cudaFuncAttributeMaxDynamicSharedMemorySize, SMEM_BYTES);

    cvtx_kernel<<<(NN * DD + 255) / 256, 256>>>(x);
    buildbt_kernel<<<(KK * DD + 255) / 256, 256>>>(wr, ws);

    dim3 grid(KK / 128, NNPAD / 128);   // (34, 391)
    mma_gemm_kernel<<<grid, 256, SMEM_BYTES>>>();

    scatter_kernel<<<(EE + 7) / 8, 256>>>(ei, et);
    relu_kernel<<<(unsigned)(((long long)NN * (DD / 4) + 255) / 256), 256>>>(bias, out);
}

// round 9
// speedup vs baseline: 5.0697x; 1.1761x over previous
#include <cuda_runtime.h>
#include <cuda_fp16.h>
#include <cstdint>

// Problem constants
#define NN 50000
#define NNPAD 50048              // 391*128; pad rows stay zero (globals zero-init)
#define DD 256
#define RR 16
#define EE 800000
#define KK (17 * DD)             // 4352 GEMM cols: 16 relation blocks + self
#define RELC (RR * DD)           // 4096 relation cols

// Scratch (device globals; zero-initialized at load; allocation-free)
__device__ __half    g_xh[(size_t)NNPAD * DD];   // x (fp16)
__device__ __half    g_bt[(size_t)KK * DD];      // B^T fp16 [j][k]
__device__ __half    g_XWrel[(size_t)NN * RELC]; // 410MB fp16 messages
__device__ float     g_self[(size_t)NN * DD];    // 51MB self term
__device__ int       g_hist[NN];                 // per-dst degree / cursor
__device__ int       g_start[NN];                // per-dst start offset
__device__ uint32_t  g_edges[EE];                // packed src | (rel<<16), dst-sorted

// ---------------------------------------------------------------------------
__device__ __forceinline__ uint32_t smem_u32(const void* p) {
    uint32_t a;
    asm("{ .reg .u64 t; cvta.to.shared.u64 t, %1; cvt.u32.u64 %0, t; }" : "=r"(a) : "l"(p));
    return a;
}

#define LDSM4(r, addr)                                                        \
    asm volatile("ldmatrix.sync.aligned.m8n8.x4.shared.b16 {%0,%1,%2,%3}, [%4];" \
        : "=r"((r)[0]), "=r"((r)[1]), "=r"((r)[2]), "=r"((r)[3]) : "r"(addr))

#define MMA(d, a, b)                                                          \
    asm volatile("mma.sync.aligned.m16n8k16.row.col.f32.f16.f16.f32 "         \
        "{%0,%1,%2,%3}, {%4,%5,%6,%7}, {%8,%9}, {%0,%1,%2,%3};"               \
        : "+f"((d)[0]), "+f"((d)[1]), "+f"((d)[2]), "+f"((d)[3])              \
        : "r"((a)[0]), "r"((a)[1]), "r"((a)[2]), "r"((a)[3]),                 \
          "r"((b)[0]), "r"((b)[1]))

#define CP16(dst, src) asm volatile("cp.async.cg.shared.global [%0], [%1], 16;" :: "r"(dst), "l"(src))
#define CP_COMMIT()    asm volatile("cp.async.commit_group;" ::: "memory")
#define CP_WAIT(n)     asm volatile("cp.async.wait_group %0;" :: "n"(n) : "memory")

// ---------------------------------------------------------------------------
// Prep 1: x fp32 -> fp16
// ---------------------------------------------------------------------------
__global__ void cvtx_kernel(const float* __restrict__ x) {
    long long i = (long long)blockIdx.x * blockDim.x + threadIdx.x;
    if (i >= (long long)NN * DD) return;
    g_xh[i] = __float2half_rn(x[i]);
}

// ---------------------------------------------------------------------------
// Prep 2: B^T fp16
// ---------------------------------------------------------------------------
__global__ void buildbt_kernel(const float* __restrict__ wr, const float* __restrict__ ws) {
    int idx = blockIdx.x * blockDim.x + threadIdx.x;
    if (idx >= KK * DD) return;
    int j = idx >> 8;
    int k = idx & 255;
    float w;
    if (j < RELC) {
        int r = j >> 8, h = j & 255;
        w = wr[((size_t)r * DD + k) * DD + h];
    } else {
        w = ws[(size_t)k * DD + (j - RELC)];
    }
    g_bt[idx] = __float2half_rn(w);
}

// ---------------------------------------------------------------------------
// Sort 1: zero histogram (graph replays the whole sequence; re-zero per call)
// ---------------------------------------------------------------------------
__global__ void zeroh_kernel() {
    int i = blockIdx.x * blockDim.x + threadIdx.x;
    if (i < NN) g_hist[i] = 0;
}

// ---------------------------------------------------------------------------
// Sort 2: histogram of dst
// ---------------------------------------------------------------------------
__global__ void hist_kernel(const int* __restrict__ ei, const int* __restrict__ et) {
    int e = blockIdx.x * blockDim.x + threadIdx.x;
    if (e >= EE) return;
    int src = ei[e], dst = ei[EE + e], rel = et[e];
    if ((unsigned)src >= NN || (unsigned)dst >= NN || (unsigned)rel >= RR) return;
    atomicAdd(&g_hist[dst], 1);
}

// ---------------------------------------------------------------------------
// Sort 3: exclusive prefix scan over g_hist -> g_start (g_hist becomes the
// reorder cursor). Single block of 1024, shuffle-based.
// ---------------------------------------------------------------------------
__global__ void scan_kernel() {
    __shared__ int sh_w[32];
    __shared__ int sh_o[32];
    __shared__ int sh_carry;
    const int tid = threadIdx.x, lane = tid & 31, warp = tid >> 5;
    if (tid == 0) sh_carry = 0;
    __syncthreads();
    for (int base = 0; base < NN; base += 1024) {
        int i = base + tid;
        int v = (i < NN) ? g_hist[i] : 0;
        int incl = v;
#pragma unroll
        for (int off = 1; off < 32; off <<= 1) {
            int t = __shfl_up_sync(0xFFFFFFFF, incl, off);
            if (lane >= off) incl += t;
        }
        if (lane == 31) sh_w[warp] = incl;
        __syncthreads();
        if (warp == 0) {
            int wv = sh_w[lane];
            int wi = wv;
#pragma unroll
            for (int off = 1; off < 32; off <<= 1) {
                int t = __shfl_up_sync(0xFFFFFFFF, wi, off);
                if (lane >= off) wi += t;
            }
            sh_o[lane] = wi - wv;        // exclusive warp offset
        }
        __syncthreads();
        int excl = sh_carry + sh_o[warp] + (incl - v);
        if (i < NN) {
            g_start[i] = excl;
            g_hist[i] = excl;            // cursor for reorder
        }
        __syncthreads();                  // everyone has read sh_carry
        if (tid == 1023) sh_carry += sh_o[31] + sh_w[31];   // += chunk total
        __syncthreads();
    }
}

// ---------------------------------------------------------------------------
// Sort 4: reorder edges into dst-sorted packed list
// ---------------------------------------------------------------------------
__global__ void reorder_kernel(const int* __restrict__ ei, const int* __restrict__ et) {
    int e = blockIdx.x * blockDim.x + threadIdx.x;
    if (e >= EE) return;
    int src = ei[e], dst = ei[EE + e], rel = et[e];
    if ((unsigned)src >= NN || (unsigned)dst >= NN || (unsigned)rel >= RR) return;
    int pos = atomicAdd(&g_hist[dst], 1);
    g_edges[pos] = (uint32_t)src | ((uint32_t)rel << 16);
}

// ---------------------------------------------------------------------------
// GEMM (unchanged from R8): x @ B via fp16 mma.sync, fp32 accum.
// ---------------------------------------------------------------------------
#define PL_OFF 10240
#define BUF_OFF 20480
#define SMEM_BYTES 40960

__global__ void __launch_bounds__(256, 2) mma_gemm_kernel() {
    extern __shared__ char sm[];
    const uint32_t sb = smem_u32(sm);
    const int tid = threadIdx.x, warp = tid >> 5, lane = tid & 31;
    const int wm = warp & 1, wn = warp >> 1;
    const size_t mBase = (size_t)blockIdx.y * 128;
    const int nBase = blockIdx.x * 128;

    float acc[4][4][4];
#pragma unroll
    for (int a = 0; a < 4; ++a)
#pragma unroll
        for (int b = 0; b < 4; ++b)
#pragma unroll
            for (int c = 0; c < 4; ++c) acc[a][b][c] = 0.f;

    auto load = [&](int c, int b) {
        const int kOff = c * 32;
        const uint32_t dbase = sb + b * BUF_OFF;
#pragma unroll
        for (int i = 0; i < 4; ++i) {
            int idx = tid + i * 256;
            int part = idx >> 9;
            int r = (idx >> 2) & 127, v = idx & 3;
            const __half* src = part
                ? g_bt + (size_t)(nBase + r) * DD + kOff + v * 8
                : g_xh + (mBase + r) * DD + kOff + v * 8;
            CP16(dbase + part * PL_OFF + r * 80 + v * 16, src);
        }
    };

    auto compute = [&](int b) {
        const uint32_t Ab = sb + b * BUF_OFF;
        const uint32_t Bb = Ab + PL_OFF;
#pragma unroll
        for (int ks = 0; ks < 2; ++ks) {
            uint32_t ah[4][4];
            const int arow = wm * 64 + (lane & 15);
            const uint32_t acol = ((lane >> 4) * 16) + ks * 32;
#pragma unroll
            for (int mt = 0; mt < 4; ++mt) {
                uint32_t ad = Ab + (uint32_t)(arow + mt * 16) * 80 + acol;
                LDSM4(ah[mt], ad);
            }
            uint32_t bh[2][4];
            const int brow = (lane & 7) + ((lane >> 4) << 3);
            const uint32_t bcol = (((lane >> 3) & 1) * 16) + ks * 32;
#pragma unroll
            for (int ng = 0; ng < 2; ++ng) {
                uint32_t bd = Bb + (uint32_t)(wn * 32 + ng * 16 + brow) * 80 + bcol;
                LDSM4(bh[ng], bd);
            }
#pragma unroll
            for (int mt = 0; mt < 4; ++mt)
#pragma unroll
                for (int nt = 0; nt < 4; ++nt) {
                    int ng = nt >> 1, j = nt & 1;
                    MMA(acc[mt][nt], ah[mt], (&bh[ng][j * 2]));
                }
        }
    };

    load(0, 0);
    CP_COMMIT();
#pragma unroll 1
    for (int c = 0; c < 8; ++c) {
        if (c < 7) {
            load(c + 1, (c + 1) & 1);
            CP_COMMIT();
            CP_WAIT(1);
        } else {
            CP_WAIT(0);
        }
        __syncthreads();
        compute(c & 1);
        __syncthreads();
    }

    const bool isRel = nBase < RELC;
#pragma unroll
    for (int mt = 0; mt < 4; ++mt) {
        int r0 = (int)mBase + wm * 64 + mt * 16 + (lane >> 2);
#pragma unroll
        for (int nt = 0; nt < 4; ++nt) {
            int col = nBase + wn * 32 + nt * 8 + 2 * (lane & 3);
            if (isRel) {
                __half2 v01 = __floats2half2_rn(acc[mt][nt][0], acc[mt][nt][1]);
                __half2 v23 = __floats2half2_rn(acc[mt][nt][2], acc[mt][nt][3]);
                if (r0 < NN)
                    *(__half2*)(g_XWrel + (size_t)r0 * RELC + col) = v01;
                if (r0 + 8 < NN)
                    *(__half2*)(g_XWrel + (size_t)(r0 + 8) * RELC + col) = v23;
            } else {
                int sc = col - RELC;
                if (r0 < NN)
                    *(float2*)(g_self + (size_t)r0 * DD + sc) =
                        make_float2(acc[mt][nt][0], acc[mt][nt][1]);
                if (r0 + 8 < NN)
                    *(float2*)(g_self + (size_t)(r0 + 8) * DD + sc) =
                        make_float2(acc[mt][nt][2], acc[mt][nt][3]);
            }
        }
    }
}

// ---------------------------------------------------------------------------
// Gather-reduce + fused epilogue: one warp per dst node, lane owns 8 floats.
// out[n] = relu(g_self[n] + sum_{edges->n} msg + bias)
// ---------------------------------------------------------------------------
__global__ void __launch_bounds__(256) gather_kernel(const float* __restrict__ bias,
                                                     float* __restrict__ out) {
    int n = blockIdx.x * 8 + (threadIdx.x >> 5);
    if (n >= NN) return;
    const int lane = threadIdx.x & 31;

    float acc[8];
#pragma unroll
    for (int j = 0; j < 8; ++j) acc[j] = 0.f;

    const int beg = g_start[n];
    const int end = g_hist[n];      // post-reorder cursor = start + count
    for (int i = beg; i < end; ++i) {
        uint32_t u = g_edges[i];
        int src = (int)(u & 0xFFFF);
        int rel = (int)(u >> 16);
        uint4 m = *(const uint4*)(g_XWrel + (size_t)src * RELC + rel * DD + lane * 8);
        float2 f0 = __half22float2(*(__half2*)&m.x);
        float2 f1 = __half22float2(*(__half2*)&m.y);
        float2 f2 = __half22float2(*(__half2*)&m.z);
        float2 f3 = __half22float2(*(__half2*)&m.w);
        acc[0] += f0.x; acc[1] += f0.y; acc[2] += f1.x; acc[3] += f1.y;
        acc[4] += f2.x; acc[5] += f2.y; acc[6] += f3.x; acc[7] += f3.y;
    }

    const float* sp = g_self + (size_t)n * DD + lane * 8;
    const float* bp = bias + lane * 8;
    float* op = out + (size_t)n * DD + lane * 8;
    float4 s0 = *(const float4*)sp, s1 = *(const float4*)(sp + 4);
    float4 b0 = *(const float4*)bp, b1 = *(const float4*)(bp + 4);
    float4 o0, o1;
    o0.x = fmaxf(s0.x + acc[0] + b0.x, 0.f);
    o0.y = fmaxf(s0.y + acc[1] + b0.y, 0.f);
    o0.z = fmaxf(s0.z + acc[2] + b0.z, 0.f);
    o0.w = fmaxf(s0.w + acc[3] + b0.w, 0.f);
    o1.x = fmaxf(s1.x + acc[4] + b1.x, 0.f);
    o1.y = fmaxf(s1.y + acc[5] + b1.y, 0.f);
    o1.z = fmaxf(s1.z + acc[6] + b1.z, 0.f);
    o1.w = fmaxf(s1.w + acc[7] + b1.w, 0.f);
    *(float4*)op = o0;
    *(float4*)(op + 4) = o1;
}

// ---------------------------------------------------------------------------
extern "C" void kernel_launch(void* const* d_in, const int* in_sizes, int n_in,
                              void* d_out, int out_size) {
    const float* x    = (const float*)d_in[0];
    const int*   ei   = (const int*)d_in[1];     // (2, E) int32
    const int*   et   = (const int*)d_in[2];     // (E,)  int32
    const float* wr   = (const float*)d_in[3];   // (16,256,256)
    const float* ws   = (const float*)d_in[4];   // (256,256)
    const float* bias = (const float*)d_in[5];   // (256,)
    float*       out  = (float*)d_out;           // (50000,256)
    (void)in_sizes; (void)n_in; (void)out_size;

    cudaFuncSetAttribute(mma_gemm_kernel, cudaFuncAttributeMaxDynamicSharedMemorySize, SMEM_BYTES);

    // prep + edge sort (independent of GEMM)
    cvtx_kernel<<<(NN * DD + 255) / 256, 256>>>(x);
    buildbt_kernel<<<(KK * DD + 255) / 256, 256>>>(wr, ws);
    zeroh_kernel<<<(NN + 255) / 256, 256>>>();
    hist_kernel<<<(EE + 255) / 256, 256>>>(ei, et);
    scan_kernel<<<1, 1024>>>();
    reorder_kernel<<<(EE + 255) / 256, 256>>>(ei, et);

    // GEMM
    dim3 grid(KK / 128, NNPAD / 128);   // (34, 391)
    mma_gemm_kernel<<<grid, 256, SMEM_BYTES>>>();

    // atomic-free aggregation + fused bias+relu epilogue
    gather_kernel<<<(NN + 7) / 8, 256>>>(bias, out);
}

// round 10
// speedup vs baseline: 5.8549x; 1.1549x over previous
#include <cuda_runtime.h>
#include <cuda_fp16.h>
#include <cstdint>

// Problem constants
#define NN 50000
#define NNPAD 50048              // 391*128; pad rows stay zero (globals zero-init)
#define DD 256
#define RR 16
#define EE 800000
#define KK (17 * DD)             // 4352 GEMM cols: 16 relation blocks + self
#define RELC (RR * DD)           // 4096 relation cols
#define SCAN_B 1024
#define NBLK ((NN + SCAN_B - 1) / SCAN_B)   // 49

// Scratch (device globals; zero-initialized at load; allocation-free)
__device__ __half    g_xh[(size_t)NNPAD * DD];   // x (fp16)
__device__ __half    g_bt[(size_t)KK * DD];      // B^T fp16 [j][k]
__device__ __half    g_XWrel[(size_t)NN * RELC]; // 410MB fp16 messages
__device__ float     g_self[(size_t)NN * DD];    // 51MB self term
__device__ int       g_hist[NN];                 // per-dst degree / cursor
__device__ int       g_start[NN];                // per-dst start offset
__device__ int       g_bsum[64];                 // per-scan-block totals
__device__ int       g_boff[64];                 // scanned block offsets
__device__ uint32_t  g_edges[EE];                // packed src | (rel<<16), dst-sorted

// ---------------------------------------------------------------------------
__device__ __forceinline__ uint32_t smem_u32(const void* p) {
    uint32_t a;
    asm("{ .reg .u64 t; cvta.to.shared.u64 t, %1; cvt.u32.u64 %0, t; }" : "=r"(a) : "l"(p));
    return a;
}

#define LDSM4(r, addr)                                                        \
    asm volatile("ldmatrix.sync.aligned.m8n8.x4.shared.b16 {%0,%1,%2,%3}, [%4];" \
        : "=r"((r)[0]), "=r"((r)[1]), "=r"((r)[2]), "=r"((r)[3]) : "r"(addr))

#define MMA(d, a, b)                                                          \
    asm volatile("mma.sync.aligned.m16n8k16.row.col.f32.f16.f16.f32 "         \
        "{%0,%1,%2,%3}, {%4,%5,%6,%7}, {%8,%9}, {%0,%1,%2,%3};"               \
        : "+f"((d)[0]), "+f"((d)[1]), "+f"((d)[2]), "+f"((d)[3])              \
        : "r"((a)[0]), "r"((a)[1]), "r"((a)[2]), "r"((a)[3]),                 \
          "r"((b)[0]), "r"((b)[1]))

#define CP16(dst, src) asm volatile("cp.async.cg.shared.global [%0], [%1], 16;" :: "r"(dst), "l"(src))
#define CP_COMMIT()    asm volatile("cp.async.commit_group;" ::: "memory")
#define CP_WAIT(n)     asm volatile("cp.async.wait_group %0;" :: "n"(n) : "memory")

// ---------------------------------------------------------------------------
// Prep 1: x fp32 -> fp16
// ---------------------------------------------------------------------------
__global__ void cvtx_kernel(const float* __restrict__ x) {
    long long i = (long long)blockIdx.x * blockDim.x + threadIdx.x;
    if (i >= (long long)NN * DD) return;
    g_xh[i] = __float2half_rn(x[i]);
}

// ---------------------------------------------------------------------------
// Prep 2: B^T fp16
// ---------------------------------------------------------------------------
__global__ void buildbt_kernel(const float* __restrict__ wr, const float* __restrict__ ws) {
    int idx = blockIdx.x * blockDim.x + threadIdx.x;
    if (idx >= KK * DD) return;
    int j = idx >> 8;
    int k = idx & 255;
    float w;
    if (j < RELC) {
        int r = j >> 8, h = j & 255;
        w = wr[((size_t)r * DD + k) * DD + h];
    } else {
        w = ws[(size_t)k * DD + (j - RELC)];
    }
    g_bt[idx] = __float2half_rn(w);
}

// ---------------------------------------------------------------------------
// Sort 1: zero histogram (graph replays the whole sequence; re-zero per call)
// ---------------------------------------------------------------------------
__global__ void zeroh_kernel() {
    int i = blockIdx.x * blockDim.x + threadIdx.x;
    if (i < NN) g_hist[i] = 0;
}

// ---------------------------------------------------------------------------
// Sort 2: histogram of dst
// ---------------------------------------------------------------------------
__global__ void hist_kernel(const int* __restrict__ ei, const int* __restrict__ et) {
    int e = blockIdx.x * blockDim.x + threadIdx.x;
    if (e >= EE) return;
    int src = ei[e], dst = ei[EE + e], rel = et[e];
    if ((unsigned)src >= NN || (unsigned)dst >= NN || (unsigned)rel >= RR) return;
    atomicAdd(&g_hist[dst], 1);
}

// ---------------------------------------------------------------------------
// Sort 3a: per-block exclusive scan of g_hist -> g_start, block totals -> g_bsum
// ---------------------------------------------------------------------------
__global__ void scan1_kernel() {
    __shared__ int sh_w[32];
    const int tid = threadIdx.x, lane = tid & 31, warp = tid >> 5;
    int i = blockIdx.x * SCAN_B + tid;
    int v = (i < NN) ? g_hist[i] : 0;
    int incl = v;
#pragma unroll
    for (int off = 1; off < 32; off <<= 1) {
        int t = __shfl_up_sync(0xFFFFFFFF, incl, off);
        if (lane >= off) incl += t;
    }
    if (lane == 31) sh_w[warp] = incl;
    __syncthreads();
    if (warp == 0) {
        int wv = sh_w[lane];
        int wi = wv;
#pragma unroll
        for (int off = 1; off < 32; off <<= 1) {
            int t = __shfl_up_sync(0xFFFFFFFF, wi, off);
            if (lane >= off) wi += t;
        }
        sh_w[lane] = wi - wv;            // exclusive warp offset
    }
    __syncthreads();
    int excl = sh_w[warp] + incl - v;
    if (i < NN) g_start[i] = excl;       // block-local exclusive
    if (tid == SCAN_B - 1) g_bsum[blockIdx.x] = excl + v;   // block total
}

// ---------------------------------------------------------------------------
// Sort 3b: 1-warp exclusive scan of block totals -> g_boff
// ---------------------------------------------------------------------------
__global__ void scan2_kernel() {
    const int lane = threadIdx.x;        // 32 threads
    int carry = 0;
    for (int base = 0; base < NBLK; base += 32) {
        int t = base + lane;
        int v = (t < NBLK) ? g_bsum[t] : 0;
        int incl = v;
#pragma unroll
        for (int off = 1; off < 32; off <<= 1) {
            int s = __shfl_up_sync(0xFFFFFFFF, incl, off);
            if (lane >= off) incl += s;
        }
        if (t < NBLK) g_boff[t] = carry + incl - v;
        carry += __shfl_sync(0xFFFFFFFF, incl, 31);
    }
}

// ---------------------------------------------------------------------------
// Sort 3c: add block offsets; init reorder cursor
// ---------------------------------------------------------------------------
__global__ void scan3_kernel() {
    int i = blockIdx.x * blockDim.x + threadIdx.x;
    if (i >= NN) return;
    int s = g_start[i] + g_boff[i >> 10];
    g_start[i] = s;
    g_hist[i] = s;                       // cursor for reorder
}

// ---------------------------------------------------------------------------
// Sort 4: reorder edges into dst-sorted packed list
// ---------------------------------------------------------------------------
__global__ void reorder_kernel(const int* __restrict__ ei, const int* __restrict__ et) {
    int e = blockIdx.x * blockDim.x + threadIdx.x;
    if (e >= EE) return;
    int src = ei[e], dst = ei[EE + e], rel = et[e];
    if ((unsigned)src >= NN || (unsigned)dst >= NN || (unsigned)rel >= RR) return;
    int pos = atomicAdd(&g_hist[dst], 1);
    g_edges[pos] = (uint32_t)src | ((uint32_t)rel << 16);
}

// ---------------------------------------------------------------------------
// GEMM: x @ B via fp16 mma.sync, fp32 accum. Tile 128x128, BK=64 (4 chunks),
// 8 warps (2x4), cp.async double buffer.
// SMEM per buffer (36864B): A[128][72] B[128][72] halves (row 144B; banks
// 36r mod 32 = 4r -> conflict-free ldmatrix)
// ---------------------------------------------------------------------------
#define PL_OFF 18432             // 128 rows * 144B
#define BUF_OFF 36864
#define SMEM_BYTES 73728

__global__ void __launch_bounds__(256, 2) mma_gemm_kernel() {
    extern __shared__ char sm[];
    const uint32_t sb = smem_u32(sm);
    const int tid = threadIdx.x, warp = tid >> 5, lane = tid & 31;
    const int wm = warp & 1, wn = warp >> 1;
    const size_t mBase = (size_t)blockIdx.y * 128;
    const int nBase = blockIdx.x * 128;

    float acc[4][4][4];
#pragma unroll
    for (int a = 0; a < 4; ++a)
#pragma unroll
        for (int b = 0; b < 4; ++b)
#pragma unroll
            for (int c = 0; c < 4; ++c) acc[a][b][c] = 0.f;

    // chunk loader: 2048 x 16B cp.async (A 1024, B 1024) -> 8/thread
    auto load = [&](int c, int b) {
        const int kOff = c * 64;
        const uint32_t dbase = sb + b * BUF_OFF;
#pragma unroll
        for (int i = 0; i < 8; ++i) {
            int idx = tid + i * 256;                 // 0..2047
            int part = idx >> 10;                    // 0:A 1:B
            int r = (idx >> 3) & 127, v = idx & 7;
            const __half* src = part
                ? g_bt + (size_t)(nBase + r) * DD + kOff + v * 8
                : g_xh + (mBase + r) * DD + kOff + v * 8;
            CP16(dbase + part * PL_OFF + r * 144 + v * 16, src);
        }
    };

    auto compute = [&](int b) {
        const uint32_t Ab = sb + b * BUF_OFF;
        const uint32_t Bb = Ab + PL_OFF;
#pragma unroll
        for (int ks = 0; ks < 4; ++ks) {
            uint32_t ah[4][4];
            const int arow = wm * 64 + (lane & 15);
            const uint32_t acol = ((lane >> 4) * 16) + ks * 32;
#pragma unroll
            for (int mt = 0; mt < 4; ++mt) {
                uint32_t ad = Ab + (uint32_t)(arow + mt * 16) * 144 + acol;
                LDSM4(ah[mt], ad);
            }
            uint32_t bh[2][4];
            const int brow = (lane & 7) + ((lane >> 4) << 3);
            const uint32_t bcol = (((lane >> 3) & 1) * 16) + ks * 32;
#pragma unroll
            for (int ng = 0; ng < 2; ++ng) {
                uint32_t bd = Bb + (uint32_t)(wn * 32 + ng * 16 + brow) * 144 + bcol;
                LDSM4(bh[ng], bd);
            }
#pragma unroll
            for (int mt = 0; mt < 4; ++mt)
#pragma unroll
                for (int nt = 0; nt < 4; ++nt) {
                    int ng = nt >> 1, j = nt & 1;
                    MMA(acc[mt][nt], ah[mt], (&bh[ng][j * 2]));
                }
        }
    };

    load(0, 0);
    CP_COMMIT();
    load(1, 1);
    CP_COMMIT();
#pragma unroll 1
    for (int c = 0; c < 4; ++c) {
        if (c < 3) { CP_WAIT(1); } else { CP_WAIT(0); }
        __syncthreads();
        compute(c & 1);
        __syncthreads();
        if (c + 2 < 4) {
            load(c + 2, c & 1);
            CP_COMMIT();
        }
    }

    const bool isRel = nBase < RELC;
#pragma unroll
    for (int mt = 0; mt < 4; ++mt) {
        int r0 = (int)mBase + wm * 64 + mt * 16 + (lane >> 2);
#pragma unroll
        for (int nt = 0; nt < 4; ++nt) {
            int col = nBase + wn * 32 + nt * 8 + 2 * (lane & 3);
            if (isRel) {
                __half2 v01 = __floats2half2_rn(acc[mt][nt][0], acc[mt][nt][1]);
                __half2 v23 = __floats2half2_rn(acc[mt][nt][2], acc[mt][nt][3]);
                if (r0 < NN)
                    *(__half2*)(g_XWrel + (size_t)r0 * RELC + col) = v01;
                if (r0 + 8 < NN)
                    *(__half2*)(g_XWrel + (size_t)(r0 + 8) * RELC + col) = v23;
            } else {
                int sc = col - RELC;
                if (r0 < NN)
                    *(float2*)(g_self + (size_t)r0 * DD + sc) =
                        make_float2(acc[mt][nt][0], acc[mt][nt][1]);
                if (r0 + 8 < NN)
                    *(float2*)(g_self + (size_t)(r0 + 8) * DD + sc) =
                        make_float2(acc[mt][nt][2], acc[mt][nt][3]);
            }
        }
    }
}

// ---------------------------------------------------------------------------
// Gather-reduce + fused epilogue: one warp per dst node, lane owns 8 floats.
// Unroll-2: two independent 512B message loads in flight.
// ---------------------------------------------------------------------------
__global__ void __launch_bounds__(256) gather_kernel(const float* __restrict__ bias,
                                                     float* __restrict__ out) {
    int n = blockIdx.x * 8 + (threadIdx.x >> 5);
    if (n >= NN) return;
    const int lane = threadIdx.x & 31;

    float acc[8];
#pragma unroll
    for (int j = 0; j < 8; ++j) acc[j] = 0.f;

    const int beg = g_start[n];
    const int end = g_hist[n];      // post-reorder cursor = start + count

    int i = beg;
    for (; i + 2 <= end; i += 2) {
        uint32_t u0 = g_edges[i];
        uint32_t u1 = g_edges[i + 1];
        const __half* p0 = g_XWrel + (size_t)(u0 & 0xFFFF) * RELC + (u0 >> 16) * DD + lane * 8;
        const __half* p1 = g_XWrel + (size_t)(u1 & 0xFFFF) * RELC + (u1 >> 16) * DD + lane * 8;
        uint4 m0 = *(const uint4*)p0;
        uint4 m1 = *(const uint4*)p1;
        float2 a0 = __half22float2(*(__half2*)&m0.x);
        float2 a1 = __half22float2(*(__half2*)&m0.y);
        float2 a2 = __half22float2(*(__half2*)&m0.z);
        float2 a3 = __half22float2(*(__half2*)&m0.w);
        acc[0] += a0.x; acc[1] += a0.y; acc[2] += a1.x; acc[3] += a1.y;
        acc[4] += a2.x; acc[5] += a2.y; acc[6] += a3.x; acc[7] += a3.y;
        float2 b0 = __half22float2(*(__half2*)&m1.x);
        float2 b1 = __half22float2(*(__half2*)&m1.y);
        float2 b2 = __half22float2(*(__half2*)&m1.z);
        float2 b3 = __half22float2(*(__half2*)&m1.w);
        acc[0] += b0.x; acc[1] += b0.y; acc[2] += b1.x; acc[3] += b1.y;
        acc[4] += b2.x; acc[5] += b2.y; acc[6] += b3.x; acc[7] += b3.y;
    }
    if (i < end) {
        uint32_t u = g_edges[i];
        const __half* p = g_XWrel + (size_t)(u & 0xFFFF) * RELC + (u >> 16) * DD + lane * 8;
        uint4 m = *(const uint4*)p;
        float2 f0 = __half22float2(*(__half2*)&m.x);
        float2 f1 = __half22float2(*(__half2*)&m.y);
        float2 f2 = __half22float2(*(__half2*)&m.z);
        float2 f3 = __half22float2(*(__half2*)&m.w);
        acc[0] += f0.x; acc[1] += f0.y; acc[2] += f1.x; acc[3] += f1.y;
        acc[4] += f2.x; acc[5] += f2.y; acc[6] += f3.x; acc[7] += f3.y;
    }

    const float* sp = g_self + (size_t)n * DD + lane * 8;
    const float* bp = bias + lane * 8;
    float* op = out + (size_t)n * DD + lane * 8;
    float4 s0 = *(const float4*)sp, s1 = *(const float4*)(sp + 4);
    float4 b0 = *(const float4*)bp, b1 = *(const float4*)(bp + 4);
    float4 o0, o1;
    o0.x = fmaxf(s0.x + acc[0] + b0.x, 0.f);
    o0.y = fmaxf(s0.y + acc[1] + b0.y, 0.f);
    o0.z = fmaxf(s0.z + acc[2] + b0.z, 0.f);
    o0.w = fmaxf(s0.w + acc[3] + b0.w, 0.f);
    o1.x = fmaxf(s1.x + acc[4] + b1.x, 0.f);
    o1.y = fmaxf(s1.y + acc[5] + b1.y, 0.f);
    o1.z = fmaxf(s1.z + acc[6] + b1.z, 0.f);
    o1.w = fmaxf(s1.w + acc[7] + b1.w, 0.f);
    *(float4*)op = o0;
    *(float4*)(op + 4) = o1;
}

// ---------------------------------------------------------------------------
extern "C" void kernel_launch(void* const* d_in, const int* in_sizes, int n_in,
                              void* d_out, int out_size) {
    const float* x    = (const float*)d_in[0];
    const int*   ei   = (const int*)d_in[1];     // (2, E) int32
    const int*   et   = (const int*)d_in[2];     // (E,)  int32
    const float* wr   = (const float*)d_in[3];   // (16,256,256)
    const float* ws   = (const float*)d_in[4];   // (256,256)
    const float* bias = (const float*)d_in[5];   // (256,)
    float*       out  = (float*)d_out;           // (50000,256)
    (void)in_sizes; (void)n_in; (void)out_size;

    cudaFuncSetAttribute(mma_gemm_kernel, cudaFuncAttributeMaxDynamicSharedMemorySize, SMEM_BYTES);

    // prep + edge sort (independent of GEMM)
    cvtx_kernel<<<(NN * DD + 255) / 256, 256>>>(x);
    buildbt_kernel<<<(KK * DD + 255) / 256, 256>>>(wr, ws);
    zeroh_kernel<<<(NN + 255) / 256, 256>>>();
    hist_kernel<<<(EE + 255) / 256, 256>>>(ei, et);
    scan1_kernel<<<NBLK, SCAN_B>>>();
    scan2_kernel<<<1, 32>>>();
    scan3_kernel<<<(NN + 255) / 256, 256>>>();
    reorder_kernel<<<(EE + 255) / 256, 256>>>(ei, et);

    // GEMM
    dim3 grid(KK / 128, NNPAD / 128);   // (34, 391)
    mma_gemm_kernel<<<grid, 256, SMEM_BYTES>>>();

    // atomic-free aggregation + fused bias+relu epilogue
    gather_kernel<<<(NN + 7) / 8, 256>>>(bias, out);
}

// round 13
// speedup vs baseline: 7.1474x; 1.2208x over previous
#include <cuda_runtime.h>
#include <cuda_fp16.h>
#include <cstdint>

// Problem constants
#define NN 50000
#define NNPAD 50048              // 391*128; rows NN..NNPAD stay zero (zero-init)
#define DD 256
#define RR 16
#define EE 800000
#define KK (17 * DD)             // 4352 B^T rows: 16 relations + self
#define NBINS (17 * NN)          // 850000 (rel-major pair bins; rel 16 = self)
#define MAXT 6700                // >= ceil(NBINS/128) + 17
#define SCAN_B 1024
#define NBLK_P ((NBINS + SCAN_B - 1) / SCAN_B)   // 831
#define NBLK_D ((NN + SCAN_B - 1) / SCAN_B)      // 49

// Scratch (device globals; zero-initialized at load; allocation-free)
__device__ __half    g_xh[(size_t)NNPAD * DD];     // x fp16 (+zero pad row NN)
__device__ __half    g_bt[(size_t)KK * DD];        // B^T fp16 [j][k]
__device__ __half    g_msgs[(size_t)NBINS * DD];   // <=435MB compact messages
__device__ int       g_pflag[NBINS];               // pair used flags
__device__ int       g_pidx[NBINS];                // scanned -> compact index
__device__ int       g_plist[NBINS];               // compact p -> src
__device__ int       g_hist[NN];                   // dst degree / cursor
__device__ int       g_start[NN];                  // dst start offsets
__device__ int       g_bsumA[1024], g_boffA[1024]; // pair-scan block sums
__device__ int       g_bsumB[64],  g_boffB[64];    // dst-scan block sums
__device__ int       g_tile_rel[MAXT], g_tile_p0[MAXT], g_tile_pend[MAXT];
__device__ int       g_ntiles;
__device__ int       g_seg16;                      // compact base of self segment
__device__ uint32_t  g_edges[EE];                  // dst-sorted msg indices

// ---------------------------------------------------------------------------
__device__ __forceinline__ uint32_t smem_u32(const void* p) {
    uint32_t a;
    asm("{ .reg .u64 t; cvta.to.shared.u64 t, %1; cvt.u32.u64 %0, t; }" : "=r"(a) : "l"(p));
    return a;
}

#define LDSM4(r, addr)                                                        \
    asm volatile("ldmatrix.sync.aligned.m8n8.x4.shared.b16 {%0,%1,%2,%3}, [%4];" \
        : "=r"((r)[0]), "=r"((r)[1]), "=r"((r)[2]), "=r"((r)[3]) : "r"(addr))

#define MMA(d, a, b)                                                          \
    asm volatile("mma.sync.aligned.m16n8k16.row.col.f32.f16.f16.f32 "         \
        "{%0,%1,%2,%3}, {%4,%5,%6,%7}, {%8,%9}, {%0,%1,%2,%3};"               \
        : "+f"((d)[0]), "+f"((d)[1]), "+f"((d)[2]), "+f"((d)[3])              \
        : "r"((a)[0]), "r"((a)[1]), "r"((a)[2]), "r"((a)[3]),                 \
          "r"((b)[0]), "r"((b)[1]))

#define CP16(dst, src) asm volatile("cp.async.cg.shared.global [%0], [%1], 16;" :: "r"(dst), "l"(src))
#define CP_COMMIT()    asm volatile("cp.async.commit_group;" ::: "memory")
#define CP_WAIT(n)     asm volatile("cp.async.wait_group %0;" :: "n"(n) : "memory")

// ---------------------------------------------------------------------------
// Prep
// ---------------------------------------------------------------------------
__global__ void cvtx_kernel(const float* __restrict__ x) {
    long long i = (long long)blockIdx.x * blockDim.x + threadIdx.x;
    if (i >= (long long)NN * DD) return;
    g_xh[i] = __float2half_rn(x[i]);
}

__global__ void buildbt_kernel(const float* __restrict__ wr, const float* __restrict__ ws) {
    int idx = blockIdx.x * blockDim.x + threadIdx.x;
    if (idx >= KK * DD) return;
    int j = idx >> 8;
    int k = idx & 255;
    float w;
    if (j < RR * DD) {
        int r = j >> 8, h = j & 255;
        w = wr[((size_t)r * DD + k) * DD + h];
    } else {
        w = ws[(size_t)k * DD + (j - RR * DD)];
    }
    g_bt[idx] = __float2half_rn(w);
}

// ---------------------------------------------------------------------------
// Init: pair flags (self bins pre-flagged) + dst histogram zero
// ---------------------------------------------------------------------------
__global__ void init_kernel() {
    int i = blockIdx.x * blockDim.x + threadIdx.x;
    if (i < NBINS) g_pflag[i] = (i >= RR * NN) ? 1 : 0;
    if (i < NN) g_hist[i] = 0;
}

// ---------------------------------------------------------------------------
// Flag used (src,rel) pairs + dst degree histogram
// ---------------------------------------------------------------------------
__global__ void flag_hist_kernel(const int* __restrict__ ei, const int* __restrict__ et) {
    int e = blockIdx.x * blockDim.x + threadIdx.x;
    if (e >= EE) return;
    int src = ei[e], dst = ei[EE + e], rel = et[e];
    if ((unsigned)src >= NN || (unsigned)dst >= NN || (unsigned)rel >= RR) return;
    g_pflag[rel * NN + src] = 1;
    atomicAdd(&g_hist[dst], 1);
}

// ---------------------------------------------------------------------------
// Scans. IMPORTANT: __device__ symbols must be dereferenced in DEVICE code —
// passing them as kernel args from host passes the host shadow address
// (the R11 bug). `which` selects the array set inside the kernel.
//   which=0: pairs  (g_pflag -> g_pidx, sums g_bsumA)
//   which=1: dst    (g_hist  -> g_start, sums g_bsumB)
// ---------------------------------------------------------------------------
__global__ void scan_blocks(int which) {
    const int* in  = which ? g_hist  : g_pflag;
    int*       out = which ? g_start : g_pidx;
    int*      bsum = which ? g_bsumB : g_bsumA;
    const int n    = which ? NN      : NBINS;
    __shared__ int sh_w[32];
    const int tid = threadIdx.x, lane = tid & 31, warp = tid >> 5;
    int i = blockIdx.x * SCAN_B + tid;
    int v = (i < n) ? in[i] : 0;
    int incl = v;
#pragma unroll
    for (int off = 1; off < 32; off <<= 1) {
        int t = __shfl_up_sync(0xFFFFFFFF, incl, off);
        if (lane >= off) incl += t;
    }
    if (lane == 31) sh_w[warp] = incl;
    __syncthreads();
    if (warp == 0) {
        int wv = sh_w[lane];
        int wi = wv;
#pragma unroll
        for (int off = 1; off < 32; off <<= 1) {
            int t = __shfl_up_sync(0xFFFFFFFF, wi, off);
            if (lane >= off) wi += t;
        }
        sh_w[lane] = wi - wv;
    }
    __syncthreads();
    int excl = sh_w[warp] + incl - v;
    if (i < n) out[i] = excl;
    if (tid == SCAN_B - 1) bsum[blockIdx.x] = excl + v;
}

__global__ void scan_tops(int which) {
    const int* bsum = which ? g_bsumB : g_bsumA;
    int*       boff = which ? g_boffB : g_boffA;
    const int  nblk = which ? NBLK_D  : NBLK_P;
    const int lane = threadIdx.x;        // 32 threads
    int carry = 0;
    for (int base = 0; base < nblk; base += 32) {
        int t = base + lane;
        int v = (t < nblk) ? bsum[t] : 0;
        int incl = v;
#pragma unroll
        for (int off = 1; off < 32; off <<= 1) {
            int s = __shfl_up_sync(0xFFFFFFFF, incl, off);
            if (lane >= off) incl += s;
        }
        if (t < nblk) boff[t] = carry + incl - v;
        carry += __shfl_sync(0xFFFFFFFF, incl, 31);
    }
}

__global__ void scan_addA() {               // pairs: g_pidx += boffA
    int i = blockIdx.x * blockDim.x + threadIdx.x;
    if (i < NBINS) g_pidx[i] += g_boffA[i >> 10];
}

__global__ void scan_addB() {               // dst: finalize g_start, init cursor
    int i = blockIdx.x * blockDim.x + threadIdx.x;
    if (i >= NN) return;
    int s = g_start[i] + g_boffB[i >> 10];
    g_start[i] = s;
    g_hist[i] = s;
}

// ---------------------------------------------------------------------------
// Pair list: compact p -> src
// ---------------------------------------------------------------------------
__global__ void plist_kernel() {
    int i = blockIdx.x * blockDim.x + threadIdx.x;
    if (i >= NBINS) return;
    if (g_pflag[i]) {
        int rel = i / NN;
        g_plist[g_pidx[i]] = i - rel * NN;
    }
}

// ---------------------------------------------------------------------------
// Tile list: segments r=0..16 cut into 128-row tiles. One block.
// ---------------------------------------------------------------------------
__global__ void tiles_kernel() {
    __shared__ int s[17], e[17], nt[17], ts[18];
    const int tid = threadIdx.x;
    if (tid < 17) {
        s[tid] = g_pidx[(size_t)tid * NN];
        e[tid] = (tid == 16) ? (g_pidx[NBINS - 1] + 1) : g_pidx[(size_t)(tid + 1) * NN];
        nt[tid] = (e[tid] - s[tid] + 127) >> 7;
    }
    __syncthreads();
    if (tid == 0) {
        ts[0] = 0;
        for (int r = 0; r < 17; ++r) ts[r + 1] = ts[r] + nt[r];
        g_ntiles = ts[17];
        g_seg16 = s[16];
    }
    __syncthreads();
    for (int r = 0; r < 17; ++r) {
        for (int k = tid; k < nt[r]; k += blockDim.x) {
            int t = ts[r] + k;
            int p0 = s[r] + k * 128;
            g_tile_rel[t] = r;
            g_tile_p0[t] = p0;
            int pe = p0 + 128;
            g_tile_pend[t] = pe < e[r] ? pe : e[r];
        }
    }
}

// ---------------------------------------------------------------------------
// Reorder edges into dst-sorted message-index list
// ---------------------------------------------------------------------------
__global__ void reorder_kernel(const int* __restrict__ ei, const int* __restrict__ et) {
    int e = blockIdx.x * blockDim.x + threadIdx.x;
    if (e >= EE) return;
    int src = ei[e], dst = ei[EE + e], rel = et[e];
    if ((unsigned)src >= NN || (unsigned)dst >= NN || (unsigned)rel >= RR) return;
    int pos = atomicAdd(&g_hist[dst], 1);
    g_edges[pos] = (uint32_t)g_pidx[rel * NN + src];
}

// ---------------------------------------------------------------------------
// Compacted GEMM: per tile, 128 gathered x-rows @ W_seg -> fp16 msgs.
// Tile 128x128 over N=256 (grid.x=2), BK=64 (4 chunks), cp.async dbl buffer.
// ---------------------------------------------------------------------------
#define PL_OFF 18432             // 128 rows * 144B
#define BUF_OFF 36864
#define SMEM_MAIN 73728
#define SMEM_BYTES (SMEM_MAIN + 512)

__global__ void __launch_bounds__(256, 2) mma_gemm_kernel() {
    extern __shared__ char sm[];
    int* sh_src = (int*)(sm + SMEM_MAIN);
    const uint32_t sb = smem_u32(sm);
    const int tid = threadIdx.x, warp = tid >> 5, lane = tid & 31;
    const int wm = warp & 1, wn = warp >> 1;
    const int ty = blockIdx.y;
    if (ty >= g_ntiles) return;
    const int rel = g_tile_rel[ty];
    const int p0 = g_tile_p0[ty];
    const int pend = g_tile_pend[ty];
    const int nBase = blockIdx.x * 128;           // 0 or 128 within DD=256

    if (tid < 128) {
        int p = p0 + tid;
        sh_src[tid] = (p < pend) ? g_plist[p] : NN;   // NN = zero pad row
    }
    __syncthreads();

    float acc[4][4][4];
#pragma unroll
    for (int a = 0; a < 4; ++a)
#pragma unroll
        for (int b = 0; b < 4; ++b)
#pragma unroll
            for (int c = 0; c < 4; ++c) acc[a][b][c] = 0.f;

    // chunk loader: 2048 x 16B cp.async (A 1024, B 1024) -> 8/thread
    auto load = [&](int c, int b) {
        const int kOff = c * 64;
        const uint32_t dbase = sb + b * BUF_OFF;
#pragma unroll
        for (int i = 0; i < 8; ++i) {
            int idx = tid + i * 256;                 // 0..2047
            int part = idx >> 10;                    // 0:A 1:B
            int r = (idx >> 3) & 127, v = idx & 7;
            const __half* src = part
                ? g_bt + (size_t)(rel * DD + nBase + r) * DD + kOff + v * 8
                : g_xh + (size_t)sh_src[r] * DD + kOff + v * 8;
            CP16(dbase + part * PL_OFF + r * 144 + v * 16, src);
        }
    };

    auto compute = [&](int b) {
        const uint32_t Ab = sb + b * BUF_OFF;
        const uint32_t Bb = Ab + PL_OFF;
#pragma unroll
        for (int ks = 0; ks < 4; ++ks) {
            uint32_t ah[4][4];
            const int arow = wm * 64 + (lane & 15);
            const uint32_t acol = ((lane >> 4) * 16) + ks * 32;
#pragma unroll
            for (int mt = 0; mt < 4; ++mt) {
                uint32_t ad = Ab + (uint32_t)(arow + mt * 16) * 144 + acol;
                LDSM4(ah[mt], ad);
            }
            uint32_t bh[2][4];
            const int brow = (lane & 7) + ((lane >> 4) << 3);
            const uint32_t bcol = (((lane >> 3) & 1) * 16) + ks * 32;
#pragma unroll
            for (int ng = 0; ng < 2; ++ng) {
                uint32_t bd = Bb + (uint32_t)(wn * 32 + ng * 16 + brow) * 144 + bcol;
                LDSM4(bh[ng], bd);
            }
#pragma unroll
            for (int mt = 0; mt < 4; ++mt)
#pragma unroll
                for (int nt = 0; nt < 4; ++nt) {
                    int ng = nt >> 1, j = nt & 1;
                    MMA(acc[mt][nt], ah[mt], (&bh[ng][j * 2]));
                }
        }
    };

    load(0, 0);
    CP_COMMIT();
    load(1, 1);
    CP_COMMIT();
#pragma unroll 1
    for (int c = 0; c < 4; ++c) {
        if (c < 3) { CP_WAIT(1); } else { CP_WAIT(0); }
        __syncthreads();
        compute(c & 1);
        __syncthreads();
        if (c + 2 < 4) {
            load(c + 2, c & 1);
            CP_COMMIT();
        }
    }

    // epilogue: fp16 message rows (uniform; self segment included)
#pragma unroll
    for (int mt = 0; mt < 4; ++mt) {
        int rr = wm * 64 + mt * 16 + (lane >> 2);
#pragma unroll
        for (int nt = 0; nt < 4; ++nt) {
            int col = nBase + wn * 32 + nt * 8 + 2 * (lane & 3);
            __half2 v01 = __floats2half2_rn(acc[mt][nt][0], acc[mt][nt][1]);
            __half2 v23 = __floats2half2_rn(acc[mt][nt][2], acc[mt][nt][3]);
            if (p0 + rr < pend)
                *(__half2*)(g_msgs + (size_t)(p0 + rr) * DD + col) = v01;
            if (p0 + rr + 8 < pend)
                *(__half2*)(g_msgs + (size_t)(p0 + rr + 8) * DD + col) = v23;
        }
    }
}

// ---------------------------------------------------------------------------
// Gather-reduce + fused epilogue: warp per dst; self row = msgs[seg16 + n].
// ---------------------------------------------------------------------------
__global__ void __launch_bounds__(256) gather_kernel(const float* __restrict__ bias,
                                                     float* __restrict__ out) {
    int n = blockIdx.x * 8 + (threadIdx.x >> 5);
    if (n >= NN) return;
    const int lane = threadIdx.x & 31;

    float acc[8];
#pragma unroll
    for (int j = 0; j < 8; ++j) acc[j] = 0.f;

    const int beg = g_start[n];
    const int end = g_hist[n];

    int i = beg;
    for (; i + 2 <= end; i += 2) {
        uint32_t u0 = g_edges[i];
        uint32_t u1 = g_edges[i + 1];
        uint4 m0 = *(const uint4*)(g_msgs + (size_t)u0 * DD + lane * 8);
        uint4 m1 = *(const uint4*)(g_msgs + (size_t)u1 * DD + lane * 8);
        float2 a0 = __half22float2(*(__half2*)&m0.x);
        float2 a1 = __half22float2(*(__half2*)&m0.y);
        float2 a2 = __half22float2(*(__half2*)&m0.z);
        float2 a3 = __half22float2(*(__half2*)&m0.w);
        acc[0] += a0.x; acc[1] += a0.y; acc[2] += a1.x; acc[3] += a1.y;
        acc[4] += a2.x; acc[5] += a2.y; acc[6] += a3.x; acc[7] += a3.y;
        float2 b0 = __half22float2(*(__half2*)&m1.x);
        float2 b1 = __half22float2(*(__half2*)&m1.y);
        float2 b2 = __half22float2(*(__half2*)&m1.z);
        float2 b3 = __half22float2(*(__half2*)&m1.w);
        acc[0] += b0.x; acc[1] += b0.y; acc[2] += b1.x; acc[3] += b1.y;
        acc[4] += b2.x; acc[5] += b2.y; acc[6] += b3.x; acc[7] += b3.y;
    }
    if (i < end) {
        uint32_t u = g_edges[i];
        uint4 m = *(const uint4*)(g_msgs + (size_t)u * DD + lane * 8);
        float2 f0 = __half22float2(*(__half2*)&m.x);
        float2 f1 = __half22float2(*(__half2*)&m.y);
        float2 f2 = __half22float2(*(__half2*)&m.z);
        float2 f3 = __half22float2(*(__half2*)&m.w);
        acc[0] += f0.x; acc[1] += f0.y; acc[2] += f1.x; acc[3] += f1.y;
        acc[4] += f2.x; acc[5] += f2.y; acc[6] += f3.x; acc[7] += f3.y;
    }

    // self term
    {
        uint4 m = *(const uint4*)(g_msgs + (size_t)(g_seg16 + n) * DD + lane * 8);
        float2 f0 = __half22float2(*(__half2*)&m.x);
        float2 f1 = __half22float2(*(__half2*)&m.y);
        float2 f2 = __half22float2(*(__half2*)&m.z);
        float2 f3 = __half22float2(*(__half2*)&m.w);
        acc[0] += f0.x; acc[1] += f0.y; acc[2] += f1.x; acc[3] += f1.y;
        acc[4] += f2.x; acc[5] += f2.y; acc[6] += f3.x; acc[7] += f3.y;
    }

    const float* bp = bias + lane * 8;
    float* op = out + (size_t)n * DD + lane * 8;
    float4 b0 = *(const float4*)bp, b1 = *(const float4*)(bp + 4);
    float4 o0, o1;
    o0.x = fmaxf(acc[0] + b0.x, 0.f);
    o0.y = fmaxf(acc[1] + b0.y, 0.f);
    o0.z = fmaxf(acc[2] + b0.z, 0.f);
    o0.w = fmaxf(acc[3] + b0.w, 0.f);
    o1.x = fmaxf(acc[4] + b1.x, 0.f);
    o1.y = fmaxf(acc[5] + b1.y, 0.f);
    o1.z = fmaxf(acc[6] + b1.z, 0.f);
    o1.w = fmaxf(acc[7] + b1.w, 0.f);
    *(float4*)op = o0;
    *(float4*)(op + 4) = o1;
}

// ---------------------------------------------------------------------------
extern "C" void kernel_launch(void* const* d_in, const int* in_sizes, int n_in,
                              void* d_out, int out_size) {
    const float* x    = (const float*)d_in[0];
    const int*   ei   = (const int*)d_in[1];     // (2, E) int32
    const int*   et   = (const int*)d_in[2];     // (E,)  int32
    const float* wr   = (const float*)d_in[3];   // (16,256,256)
    const float* ws   = (const float*)d_in[4];   // (256,256)
    const float* bias = (const float*)d_in[5];   // (256,)
    float*       out  = (float*)d_out;           // (50000,256)
    (void)in_sizes; (void)n_in; (void)out_size;

    cudaFuncSetAttribute(mma_gemm_kernel, cudaFuncAttributeMaxDynamicSharedMemorySize, SMEM_BYTES);

    // prep
    cvtx_kernel<<<(NN * DD + 255) / 256, 256>>>(x);
    buildbt_kernel<<<(KK * DD + 255) / 256, 256>>>(wr, ws);

    // pair flags + dst histogram
    init_kernel<<<(NBINS + 255) / 256, 256>>>();
    flag_hist_kernel<<<(EE + 255) / 256, 256>>>(ei, et);

    // pair compaction scan (which=0)
    scan_blocks<<<NBLK_P, SCAN_B>>>(0);
    scan_tops<<<1, 32>>>(0);
    scan_addA<<<(NBINS + 255) / 256, 256>>>();
    plist_kernel<<<(NBINS + 255) / 256, 256>>>();
    tiles_kernel<<<1, 256>>>();

    // dst-degree scan (which=1) + edge reorder
    scan_blocks<<<NBLK_D, SCAN_B>>>(1);
    scan_tops<<<1, 32>>>(1);
    scan_addB<<<(NN + 255) / 256, 256>>>();
    reorder_kernel<<<(EE + 255) / 256, 256>>>(ei, et);

    // compacted message GEMM
    dim3 grid(2, MAXT);
    mma_gemm_kernel<<<grid, 256, SMEM_BYTES>>>();

    // gather + self + bias + relu
    gather_kernel<<<(NN + 7) / 8, 256>>>(bias, out);
}

// round 14
// speedup vs baseline: 7.4426x; 1.0413x over previous
#include <cuda_runtime.h>
#include <cuda_fp16.h>
#include <cstdint>

// Problem constants
#define NN 50000
#define NNPAD 50048              // 391*128; rows NN..NNPAD stay zero (zero-init)
#define DD 256
#define RR 16
#define EE 800000
#define KK (17 * DD)             // 4352 B^T rows: 16 relations + self
#define NBINS (17 * NN)          // 850000 (rel-major pair bins; rel 16 = self)
#define MAXT 6700                // >= ceil(NBINS/128) + 17
#define SCAN_B 1024
#define NBLK_P ((NBINS + SCAN_B - 1) / SCAN_B)   // 831
#define NBLK_D ((NN + SCAN_B - 1) / SCAN_B)      // 49

// Scratch (device globals; zero-initialized at load; allocation-free)
__device__ __half    g_xh[(size_t)NNPAD * DD];     // x fp16 (+zero pad row NN)
__device__ __half    g_bt[(size_t)KK * DD];        // B^T fp16 [j][k]
__device__ __half    g_msgs[(size_t)NBINS * DD];   // <=435MB compact messages
__device__ int       g_pflag[NBINS];               // pair used flags
__device__ int       g_pidx[NBINS];                // scanned -> compact index
__device__ int       g_plist[NBINS];               // compact p -> src
__device__ int       g_hist[NN];                   // dst degree / cursor
__device__ int       g_start[NN];                  // dst start offsets
__device__ int       g_bsumA[1024], g_boffA[1024]; // pair-scan block sums
__device__ int       g_bsumB[64],  g_boffB[64];    // dst-scan block sums
__device__ int       g_tile_rel[MAXT], g_tile_p0[MAXT], g_tile_pend[MAXT];
__device__ int       g_ntiles;
__device__ int       g_seg16;                      // compact base of self segment
__device__ uint32_t  g_edges[EE];                  // dst-sorted msg indices

// ---------------------------------------------------------------------------
__device__ __forceinline__ uint32_t smem_u32(const void* p) {
    uint32_t a;
    asm("{ .reg .u64 t; cvta.to.shared.u64 t, %1; cvt.u32.u64 %0, t; }" : "=r"(a) : "l"(p));
    return a;
}

#define LDSM4(r, addr)                                                        \
    asm volatile("ldmatrix.sync.aligned.m8n8.x4.shared.b16 {%0,%1,%2,%3}, [%4];" \
        : "=r"((r)[0]), "=r"((r)[1]), "=r"((r)[2]), "=r"((r)[3]) : "r"(addr))

#define MMA(d, a, b)                                                          \
    asm volatile("mma.sync.aligned.m16n8k16.row.col.f32.f16.f16.f32 "         \
        "{%0,%1,%2,%3}, {%4,%5,%6,%7}, {%8,%9}, {%0,%1,%2,%3};"               \
        : "+f"((d)[0]), "+f"((d)[1]), "+f"((d)[2]), "+f"((d)[3])              \
        : "r"((a)[0]), "r"((a)[1]), "r"((a)[2]), "r"((a)[3]),                 \
          "r"((b)[0]), "r"((b)[1]))

#define CP16(dst, src) asm volatile("cp.async.cg.shared.global [%0], [%1], 16;" :: "r"(dst), "l"(src))
#define CP_COMMIT()    asm volatile("cp.async.commit_group;" ::: "memory")
#define CP_WAIT(n)     asm volatile("cp.async.wait_group %0;" :: "n"(n) : "memory")

// ---------------------------------------------------------------------------
// Prep 1: x fp32 -> fp16
// ---------------------------------------------------------------------------
__global__ void cvtx_kernel(const float* __restrict__ x) {
    long long i = (long long)blockIdx.x * blockDim.x + threadIdx.x;
    if (i >= (long long)NN * DD) return;
    g_xh[i] = __float2half_rn(x[i]);
}

// ---------------------------------------------------------------------------
// Prep 2 (fused): B^T build + pair-flag init (self bins pre-flagged) + hist zero
// grid covers KK*DD = 1,114,112 >= NBINS >= NN
// ---------------------------------------------------------------------------
__global__ void prep2_kernel(const float* __restrict__ wr, const float* __restrict__ ws) {
    int idx = blockIdx.x * blockDim.x + threadIdx.x;
    if (idx < KK * DD) {
        int j = idx >> 8;
        int k = idx & 255;
        float w;
        if (j < RR * DD) {
            int r = j >> 8, h = j & 255;
            w = wr[((size_t)r * DD + k) * DD + h];
        } else {
            w = ws[(size_t)k * DD + (j - RR * DD)];
        }
        g_bt[idx] = __float2half_rn(w);
    }
    if (idx < NBINS) g_pflag[idx] = (idx >= RR * NN) ? 1 : 0;
    if (idx < NN) g_hist[idx] = 0;
}

// ---------------------------------------------------------------------------
// Flag used (src,rel) pairs + dst degree histogram
// ---------------------------------------------------------------------------
__global__ void flag_hist_kernel(const int* __restrict__ ei, const int* __restrict__ et) {
    int e = blockIdx.x * blockDim.x + threadIdx.x;
    if (e >= EE) return;
    int src = ei[e], dst = ei[EE + e], rel = et[e];
    if ((unsigned)src >= NN || (unsigned)dst >= NN || (unsigned)rel >= RR) return;
    g_pflag[rel * NN + src] = 1;
    atomicAdd(&g_hist[dst], 1);
}

// ---------------------------------------------------------------------------
// Scans. __device__ symbols dereferenced in device code only (R11 lesson).
//   which=0: pairs  (g_pflag -> g_pidx, sums g_bsumA)
//   which=1: dst    (g_hist  -> g_start, sums g_bsumB)
// ---------------------------------------------------------------------------
__global__ void scan_blocks(int which) {
    const int* in  = which ? g_hist  : g_pflag;
    int*       out = which ? g_start : g_pidx;
    int*      bsum = which ? g_bsumB : g_bsumA;
    const int n    = which ? NN      : NBINS;
    __shared__ int sh_w[32];
    const int tid = threadIdx.x, lane = tid & 31, warp = tid >> 5;
    int i = blockIdx.x * SCAN_B + tid;
    int v = (i < n) ? in[i] : 0;
    int incl = v;
#pragma unroll
    for (int off = 1; off < 32; off <<= 1) {
        int t = __shfl_up_sync(0xFFFFFFFF, incl, off);
        if (lane >= off) incl += t;
    }
    if (lane == 31) sh_w[warp] = incl;
    __syncthreads();
    if (warp == 0) {
        int wv = sh_w[lane];
        int wi = wv;
#pragma unroll
        for (int off = 1; off < 32; off <<= 1) {
            int t = __shfl_up_sync(0xFFFFFFFF, wi, off);
            if (lane >= off) wi += t;
        }
        sh_w[lane] = wi - wv;
    }
    __syncthreads();
    int excl = sh_w[warp] + incl - v;
    if (i < n) out[i] = excl;
    if (tid == SCAN_B - 1) bsum[blockIdx.x] = excl + v;
}

__global__ void scan_tops(int which) {
    const int* bsum = which ? g_bsumB : g_bsumA;
    int*       boff = which ? g_boffB : g_boffA;
    const int  nblk = which ? NBLK_D  : NBLK_P;
    const int lane = threadIdx.x;        // 32 threads
    int carry = 0;
    for (int base = 0; base < nblk; base += 32) {
        int t = base + lane;
        int v = (t < nblk) ? bsum[t] : 0;
        int incl = v;
#pragma unroll
        for (int off = 1; off < 32; off <<= 1) {
            int s = __shfl_up_sync(0xFFFFFFFF, incl, off);
            if (lane >= off) incl += s;
        }
        if (t < nblk) boff[t] = carry + incl - v;
        carry += __shfl_sync(0xFFFFFFFF, incl, 31);
    }
}

// finalize pairs: g_pidx += boffA, and emit plist in the same pass
__global__ void finalizeA_kernel() {
    int i = blockIdx.x * blockDim.x + threadIdx.x;
    if (i >= NBINS) return;
    int p = g_pidx[i] + g_boffA[i >> 10];
    g_pidx[i] = p;
    if (g_pflag[i]) {
        int rel = i / NN;
        g_plist[p] = i - rel * NN;
    }
}

__global__ void scan_addB() {               // dst: finalize g_start, init cursor
    int i = blockIdx.x * blockDim.x + threadIdx.x;
    if (i >= NN) return;
    int s = g_start[i] + g_boffB[i >> 10];
    g_start[i] = s;
    g_hist[i] = s;
}

// ---------------------------------------------------------------------------
// Tile list: segments r=0..16 cut into 128-row tiles. One block.
// ---------------------------------------------------------------------------
__global__ void tiles_kernel() {
    __shared__ int s[17], e[17], nt[17], ts[18];
    const int tid = threadIdx.x;
    if (tid < 17) {
        s[tid] = g_pidx[(size_t)tid * NN];
        e[tid] = (tid == 16) ? (g_pidx[NBINS - 1] + 1) : g_pidx[(size_t)(tid + 1) * NN];
        nt[tid] = (e[tid] - s[tid] + 127) >> 7;
    }
    __syncthreads();
    if (tid == 0) {
        ts[0] = 0;
        for (int r = 0; r < 17; ++r) ts[r + 1] = ts[r] + nt[r];
        g_ntiles = ts[17];
        g_seg16 = s[16];
    }
    __syncthreads();
    for (int r = 0; r < 17; ++r) {
        for (int k = tid; k < nt[r]; k += blockDim.x) {
            int t = ts[r] + k;
            int p0 = s[r] + k * 128;
            g_tile_rel[t] = r;
            g_tile_p0[t] = p0;
            int pe = p0 + 128;
            g_tile_pend[t] = pe < e[r] ? pe : e[r];
        }
    }
}

// ---------------------------------------------------------------------------
// Reorder edges into dst-sorted message-index list
// ---------------------------------------------------------------------------
__global__ void reorder_kernel(const int* __restrict__ ei, const int* __restrict__ et) {
    int e = blockIdx.x * blockDim.x + threadIdx.x;
    if (e >= EE) return;
    int src = ei[e], dst = ei[EE + e], rel = et[e];
    if ((unsigned)src >= NN || (unsigned)dst >= NN || (unsigned)rel >= RR) return;
    int pos = atomicAdd(&g_hist[dst], 1);
    g_edges[pos] = (uint32_t)g_pidx[rel * NN + src];
}

// ---------------------------------------------------------------------------
// Compacted GEMM: per tile, 128 gathered x-rows @ W_seg -> fp16 msgs.
// Tile 128x128 over N=256 (grid.x=2), BK=64 (4 chunks), cp.async dbl buffer.
// ---------------------------------------------------------------------------
#define PL_OFF 18432             // 128 rows * 144B
#define BUF_OFF 36864
#define SMEM_MAIN 73728
#define SMEM_BYTES (SMEM_MAIN + 512)

__global__ void __launch_bounds__(256, 2) mma_gemm_kernel() {
    extern __shared__ char sm[];
    int* sh_src = (int*)(sm + SMEM_MAIN);
    const uint32_t sb = smem_u32(sm);
    const int tid = threadIdx.x, warp = tid >> 5, lane = tid & 31;
    const int wm = warp & 1, wn = warp >> 1;
    const int ty = blockIdx.y;
    if (ty >= g_ntiles) return;
    const int rel = g_tile_rel[ty];
    const int p0 = g_tile_p0[ty];
    const int pend = g_tile_pend[ty];
    const int nBase = blockIdx.x * 128;           // 0 or 128 within DD=256

    if (tid < 128) {
        int p = p0 + tid;
        sh_src[tid] = (p < pend) ? g_plist[p] : NN;   // NN = zero pad row
    }
    __syncthreads();

    float acc[4][4][4];
#pragma unroll
    for (int a = 0; a < 4; ++a)
#pragma unroll
        for (int b = 0; b < 4; ++b)
#pragma unroll
            for (int c = 0; c < 4; ++c) acc[a][b][c] = 0.f;

    // chunk loader: 2048 x 16B cp.async (A 1024, B 1024) -> 8/thread
    auto load = [&](int c, int b) {
        const int kOff = c * 64;
        const uint32_t dbase = sb + b * BUF_OFF;
#pragma unroll
        for (int i = 0; i < 8; ++i) {
            int idx = tid + i * 256;                 // 0..2047
            int part = idx >> 10;                    // 0:A 1:B
            int r = (idx >> 3) & 127, v = idx & 7;
            const __half* src = part
                ? g_bt + (size_t)(rel * DD + nBase + r) * DD + kOff + v * 8
                : g_xh + (size_t)sh_src[r] * DD + kOff + v * 8;
            CP16(dbase + part * PL_OFF + r * 144 + v * 16, src);
        }
    };

    auto compute = [&](int b) {
        const uint32_t Ab = sb + b * BUF_OFF;
        const uint32_t Bb = Ab + PL_OFF;
#pragma unroll
        for (int ks = 0; ks < 4; ++ks) {
            uint32_t ah[4][4];
            const int arow = wm * 64 + (lane & 15);
            const uint32_t acol = ((lane >> 4) * 16) + ks * 32;
#pragma unroll
            for (int mt = 0; mt < 4; ++mt) {
                uint32_t ad = Ab + (uint32_t)(arow + mt * 16) * 144 + acol;
                LDSM4(ah[mt], ad);
            }
            uint32_t bh[2][4];
            const int brow = (lane & 7) + ((lane >> 4) << 3);
            const uint32_t bcol = (((lane >> 3) & 1) * 16) + ks * 32;
#pragma unroll
            for (int ng = 0; ng < 2; ++ng) {
                uint32_t bd = Bb + (uint32_t)(wn * 32 + ng * 16 + brow) * 144 + bcol;
                LDSM4(bh[ng], bd);
            }
#pragma unroll
            for (int mt = 0; mt < 4; ++mt)
#pragma unroll
                for (int nt = 0; nt < 4; ++nt) {
                    int ng = nt >> 1, j = nt & 1;
                    MMA(acc[mt][nt], ah[mt], (&bh[ng][j * 2]));
                }
        }
    };

    load(0, 0);
    CP_COMMIT();
    load(1, 1);
    CP_COMMIT();
#pragma unroll 1
    for (int c = 0; c < 4; ++c) {
        if (c < 3) { CP_WAIT(1); } else { CP_WAIT(0); }
        __syncthreads();
        compute(c & 1);
        __syncthreads();
        if (c + 2 < 4) {
            load(c + 2, c & 1);
            CP_COMMIT();
        }
    }

    // epilogue: fp16 message rows (uniform; self segment included)
#pragma unroll
    for (int mt = 0; mt < 4; ++mt) {
        int rr = wm * 64 + mt * 16 + (lane >> 2);
#pragma unroll
        for (int nt = 0; nt < 4; ++nt) {
            int col = nBase + wn * 32 + nt * 8 + 2 * (lane & 3);
            __half2 v01 = __floats2half2_rn(acc[mt][nt][0], acc[mt][nt][1]);
            __half2 v23 = __floats2half2_rn(acc[mt][nt][2], acc[mt][nt][3]);
            if (p0 + rr < pend)
                *(__half2*)(g_msgs + (size_t)(p0 + rr) * DD + col) = v01;
            if (p0 + rr + 8 < pend)
                *(__half2*)(g_msgs + (size_t)(p0 + rr + 8) * DD + col) = v23;
        }
    }
}

// ---------------------------------------------------------------------------
// Gather-reduce + fused epilogue: warp per dst; self row = msgs[seg16 + n].
// Unroll-4 for MLP on the random 512B message stream.
// ---------------------------------------------------------------------------
__device__ __forceinline__ void acc_msg(float* acc, const uint4& m) {
    float2 f0 = __half22float2(*(__half2*)&m.x);
    float2 f1 = __half22float2(*(__half2*)&m.y);
    float2 f2 = __half22float2(*(__half2*)&m.z);
    float2 f3 = __half22float2(*(__half2*)&m.w);
    acc[0] += f0.x; acc[1] += f0.y; acc[2] += f1.x; acc[3] += f1.y;
    acc[4] += f2.x; acc[5] += f2.y; acc[6] += f3.x; acc[7] += f3.y;
}

__global__ void __launch_bounds__(256) gather_kernel(const float* __restrict__ bias,
                                                     float* __restrict__ out) {
    int n = blockIdx.x * 8 + (threadIdx.x >> 5);
    if (n >= NN) return;
    const int lane = threadIdx.x & 31;

    float acc[8];
#pragma unroll
    for (int j = 0; j < 8; ++j) acc[j] = 0.f;

    const int beg = g_start[n];
    const int end = g_hist[n];

    int i = beg;
    for (; i + 4 <= end; i += 4) {
        uint32_t u0 = g_edges[i], u1 = g_edges[i + 1];
        uint32_t u2 = g_edges[i + 2], u3 = g_edges[i + 3];
        uint4 m0 = *(const uint4*)(g_msgs + (size_t)u0 * DD + lane * 8);
        uint4 m1 = *(const uint4*)(g_msgs + (size_t)u1 * DD + lane * 8);
        uint4 m2 = *(const uint4*)(g_msgs + (size_t)u2 * DD + lane * 8);
        uint4 m3 = *(const uint4*)(g_msgs + (size_t)u3 * DD + lane * 8);
        acc_msg(acc, m0);
        acc_msg(acc, m1);
        acc_msg(acc, m2);
        acc_msg(acc, m3);
    }
    for (; i < end; ++i) {
        uint32_t u = g_edges[i];
        uint4 m = *(const uint4*)(g_msgs + (size_t)u * DD + lane * 8);
        acc_msg(acc, m);
    }

    // self term
    {
        uint4 m = *(const uint4*)(g_msgs + (size_t)(g_seg16 + n) * DD + lane * 8);
        acc_msg(acc, m);
    }

    const float* bp = bias + lane * 8;
    float* op = out + (size_t)n * DD + lane * 8;
    float4 b0 = *(const float4*)bp, b1 = *(const float4*)(bp + 4);
    float4 o0, o1;
    o0.x = fmaxf(acc[0] + b0.x, 0.f);
    o0.y = fmaxf(acc[1] + b0.y, 0.f);
    o0.z = fmaxf(acc[2] + b0.z, 0.f);
    o0.w = fmaxf(acc[3] + b0.w, 0.f);
    o1.x = fmaxf(acc[4] + b1.x, 0.f);
    o1.y = fmaxf(acc[5] + b1.y, 0.f);
    o1.z = fmaxf(acc[6] + b1.z, 0.f);
    o1.w = fmaxf(acc[7] + b1.w, 0.f);
    *(float4*)op = o0;
    *(float4*)(op + 4) = o1;
}

// ---------------------------------------------------------------------------
extern "C" void kernel_launch(void* const* d_in, const int* in_sizes, int n_in,
                              void* d_out, int out_size) {
    const float* x    = (const float*)d_in[0];
    const int*   ei   = (const int*)d_in[1];     // (2, E) int32
    const int*   et   = (const int*)d_in[2];     // (E,)  int32
    const float* wr   = (const float*)d_in[3];   // (16,256,256)
    const float* ws   = (const float*)d_in[4];   // (256,256)
    const float* bias = (const float*)d_in[5];   // (256,)
    float*       out  = (float*)d_out;           // (50000,256)
    (void)in_sizes; (void)n_in; (void)out_size;

    // Side stream + fork/join events. Created on the FIRST (uncaptured,
    // correctness) call; during graph capture these already exist, so no
    // forbidden APIs run inside capture. Host-object creation only — no
    // device memory involved.
    static cudaStream_t s_side = nullptr;
    static cudaEvent_t evFork = nullptr, evJoin = nullptr;
    if (s_side == nullptr) {
        cudaStreamCreateWithFlags(&s_side, cudaStreamNonBlocking);
        cudaEventCreateWithFlags(&evFork, cudaEventDisableTiming);
        cudaEventCreateWithFlags(&evJoin, cudaEventDisableTiming);
    }

    cudaFuncSetAttribute(mma_gemm_kernel, cudaFuncAttributeMaxDynamicSharedMemorySize, SMEM_BYTES);

    // ---- main stream: prep + pair compaction ----
    cvtx_kernel<<<(NN * DD + 255) / 256, 256>>>(x);
    prep2_kernel<<<(KK * DD + 255) / 256, 256>>>(wr, ws);
    flag_hist_kernel<<<(EE + 255) / 256, 256>>>(ei, et);
    scan_blocks<<<NBLK_P, SCAN_B>>>(0);
    scan_tops<<<1, 32>>>(0);
    finalizeA_kernel<<<(NBINS + 255) / 256, 256>>>();

    // ---- fork: dst-scan + reorder run concurrently with tiles + GEMM ----
    cudaEventRecord(evFork, 0);
    cudaStreamWaitEvent(s_side, evFork, 0);
    scan_blocks<<<NBLK_D, SCAN_B, 0, s_side>>>(1);
    scan_tops<<<1, 32, 0, s_side>>>(1);
    scan_addB<<<(NN + 255) / 256, 256, 0, s_side>>>();
    reorder_kernel<<<(EE + 255) / 256, 256, 0, s_side>>>(ei, et);
    cudaEventRecord(evJoin, s_side);

    // ---- main stream: tiles + compacted message GEMM ----
    tiles_kernel<<<1, 256>>>();
    dim3 grid(2, MAXT);
    mma_gemm_kernel<<<grid, 256, SMEM_BYTES>>>();

    // ---- join, then gather + self + bias + relu ----
    cudaStreamWaitEvent(0, evJoin, 0);
    gather_kernel<<<(NN + 7) / 8, 256>>>(bias, out);
}